// round 6
// baseline (speedup 1.0000x reference)
#include <cuda_runtime.h>
#include <cuda_fp16.h>
#include <math.h>

// Problem constants
#define Bb   8
#define Tt   128
#define Nn   512
#define HIDc 4
#define Dd   2048
#define Ee   16384
#define FD   8192
#define NEG  0.2f

// ---------------- device scratch (no allocations allowed) ----------------
__device__ __align__(256) float g_seq[1024 * 2048];   // [T*B, D] GAT output, 8 MB
__device__ __align__(256) float g_zx[1024u * 8192u];  // [T*B, 4D] x@Wih^T + bias, 32 MB
__device__ __align__(256) __half g_whh_h[4u * Dd * Dd]; // fp16 w_hh, 32 MB
__device__ __align__(256) float g_h[2][Bb * Dd];      // double-buffered hidden
__device__ int   g_bar[Tt];                            // per-step grid barrier counters
__device__ int   g_deg[Nn];
__device__ int   g_off[Nn];
__device__ int   g_cur[Nn];
__device__ int   g_csr[Ee];
__device__ float g_cs, g_cd;

// ---------------- f32x2 packed FMA helpers (sm_100+) ----------------
typedef unsigned long long ull;

__device__ __forceinline__ ull pk2(float x, float y) {
    ull r;
    asm("mov.b64 %0, {%1, %2};" : "=l"(r) : "f"(x), "f"(y));
    return r;
}
__device__ __forceinline__ void ffma2(ull &d, ull a, ull b) {
    asm("fma.rn.f32x2 %0, %1, %2, %0;" : "+l"(d) : "l"(a), "l"(b));
}
__device__ __forceinline__ float fsum2(ull v) {
    float x, y;
    asm("mov.b64 {%0, %1}, %2;" : "=f"(x), "=f"(y) : "l"(v));
    return x + y;
}
__device__ __forceinline__ void upk2(ull v, float &x, float &y) {
    asm("mov.b64 {%0, %1}, %2;" : "=f"(x), "=f"(y) : "l"(v));
}
// unpack a uint holding half2 -> packed f32x2 ull
__device__ __forceinline__ ull h2f2(unsigned u) {
    __half2 h = *reinterpret_cast<__half2*>(&u);
    float2 f = __half22float2(h);
    return pk2(f.x, f.y);
}

// ---------------- w_hh fp32 -> fp16 ----------------
__global__ void k_wcvt(const float* __restrict__ whh) {
    unsigned idx = blockIdx.x * 512 + threadIdx.x;        // float4 index
    const unsigned total = 4u * Dd * Dd / 4;              // 4.19M
    uint2* out = (uint2*)g_whh_h;
    for (unsigned i = idx; i < total; i += gridDim.x * 512) {
        float4 v = *(const float4*)(whh + (size_t)i * 4);
        __half2 a = __floats2half2_rn(v.x, v.y);
        __half2 b = __floats2half2_rn(v.z, v.w);
        out[i] = make_uint2(*reinterpret_cast<unsigned*>(&a),
                            *reinterpret_cast<unsigned*>(&b));
    }
}

// ---------------- GAT preprocessing ----------------
__global__ void k_prep(const float* __restrict__ W, const float* __restrict__ as_,
                       const float* __restrict__ ad_) {
    int i = blockIdx.x * blockDim.x + threadIdx.x;
    if (i < Nn) g_deg[i] = 0;
    if (i < Tt) g_bar[i] = 0;              // clear grid-barrier counters each call
    if (i == 0) {
        float cs = 0.f, cd = 0.f;
        for (int k = 0; k < HIDc; k++) { cs += W[k] * as_[k]; cd += W[k] * ad_[k]; }
        g_cs = cs; g_cd = cd;
    }
}

__global__ void k_deg(const int* __restrict__ ei) {
    int e = blockIdx.x * 256 + threadIdx.x;
    if (e < Ee) atomicAdd(&g_deg[ei[Ee + e]], 1);
}

__global__ void k_scan() {
    __shared__ int s[Nn];
    int i = threadIdx.x;
    int d = g_deg[i];
    s[i] = d;
    __syncthreads();
    for (int off = 1; off < Nn; off <<= 1) {
        int t = 0;
        if (i >= off) t = s[i - off];
        __syncthreads();
        s[i] += t;
        __syncthreads();
    }
    g_off[i] = s[i] - d;
    g_cur[i] = s[i] - d;
}

__global__ void k_fill(const int* __restrict__ ei) {
    int e = blockIdx.x * 256 + threadIdx.x;
    if (e < Ee) {
        int src = ei[e];
        int dst = ei[Ee + e];
        int pos = atomicAdd(&g_cur[dst], 1);
        g_csr[pos] = src;
    }
}

// GAT for batch-0 nodes (the only ones with real incoming edges). One block per t.
__global__ void k_gat_b0(const float* __restrict__ x, const float* __restrict__ W,
                         const float* __restrict__ bias) {
    __shared__ float xs[Nn];
    int t = blockIdx.x;
    int i = threadIdx.x;
    xs[i] = x[t * Nn + i];
    __syncthreads();
    float cs = g_cs, cd = g_cd;
    float xi = xs[i];
    float es = xi * (cs + cd);
    es = es > 0.f ? es : NEG * es;
    int beg = g_off[i], end = beg + g_deg[i];
    float m = es;
    for (int e = beg; e < end; e++) {
        float v = cs * xs[g_csr[e]] + cd * xi;
        v = v > 0.f ? v : NEG * v;
        m = fmaxf(m, v);
    }
    float den = expf(es - m);
    float ssum = den * xi;
    for (int e = beg; e < end; e++) {
        float xsrc = xs[g_csr[e]];
        float v = cs * xsrc + cd * xi;
        v = v > 0.f ? v : NEG * v;
        float w = expf(v - m);
        den += w;
        ssum += w * xsrc;
    }
    float s = ssum / den;
    float* o = &g_seq[(size_t)(t * Bb + 0) * Dd + i * HIDc];
#pragma unroll
    for (int k = 0; k < HIDc; k++) {
        float g = fmaf(s, W[k], bias[k]);
        o[k] = g > 0.f ? g : 0.f;
    }
}

// GAT for batches 1..7: self-loop only => s = x
__global__ void k_gat_rest(const float* __restrict__ x, const float* __restrict__ W,
                           const float* __restrict__ bias) {
    int idx = blockIdx.x * 256 + threadIdx.x;
    if (idx >= Tt * (Bb - 1) * Nn) return;
    int t = idx / ((Bb - 1) * Nn);
    int r = idx - t * (Bb - 1) * Nn;
    int b = 1 + (r >> 9);
    int n = r & (Nn - 1);
    float xi = x[((size_t)b * Tt + t) * Nn + n];
    float* o = &g_seq[(size_t)(t * Bb + b) * Dd + n * HIDc];
#pragma unroll
    for (int k = 0; k < HIDc; k++) {
        float g = fmaf(xi, W[k], bias[k]);
        o[k] = g > 0.f ? g : 0.f;
    }
}

// ---------------- input GEMM: Zx[1024,8192] = seq @ w_ih^T + (b_ih+b_hh) ----------------
__global__ void __launch_bounds__(256, 2)
k_zx(const float* __restrict__ Bw, const float* __restrict__ bih,
     const float* __restrict__ bhh) {
    __shared__ __align__(16) float As[16][132];
    __shared__ __align__(16) float Bs[16][132];
    int tid = threadIdx.x;
    int lr = tid >> 2;
    int lk = (tid & 3) * 4;
    int bm = blockIdx.y * 128;
    int bn = blockIdx.x * 128;
    const float* Ap = g_seq + (size_t)(bm + lr) * Dd + lk;
    const float* Bp = Bw + (size_t)(bn + lr) * Dd + lk;
    int tx = tid & 15, ty = tid >> 4;

    ull acc[8][4];
#pragma unroll
    for (int i = 0; i < 8; i++)
#pragma unroll
        for (int j = 0; j < 4; j++) acc[i][j] = pk2(0.f, 0.f);

    for (int k0 = 0; k0 < Dd; k0 += 16) {
#pragma unroll
        for (int hh = 0; hh < 2; hh++) {
            float4 va = *(const float4*)(Ap + (size_t)hh * 64 * Dd + k0);
            As[lk + 0][lr + hh * 64] = va.x;
            As[lk + 1][lr + hh * 64] = va.y;
            As[lk + 2][lr + hh * 64] = va.z;
            As[lk + 3][lr + hh * 64] = va.w;
            float4 vb = *(const float4*)(Bp + (size_t)hh * 64 * Dd + k0);
            Bs[lk + 0][lr + hh * 64] = vb.x;
            Bs[lk + 1][lr + hh * 64] = vb.y;
            Bs[lk + 2][lr + hh * 64] = vb.z;
            Bs[lk + 3][lr + hh * 64] = vb.w;
        }
        __syncthreads();
#pragma unroll
        for (int kk = 0; kk < 16; kk++) {
            float4 a0 = *(const float4*)(&As[kk][ty * 8]);
            float4 a1 = *(const float4*)(&As[kk][ty * 8 + 4]);
            ulonglong2 b0 = *(const ulonglong2*)(&Bs[kk][tx * 8]);
            ulonglong2 b1 = *(const ulonglong2*)(&Bs[kk][tx * 8 + 4]);
            float av[8] = {a0.x, a0.y, a0.z, a0.w, a1.x, a1.y, a1.z, a1.w};
#pragma unroll
            for (int i = 0; i < 8; i++) {
                ull ad = pk2(av[i], av[i]);
                ffma2(acc[i][0], ad, b0.x);
                ffma2(acc[i][1], ad, b0.y);
                ffma2(acc[i][2], ad, b1.x);
                ffma2(acc[i][3], ad, b1.y);
            }
        }
        __syncthreads();
    }
#pragma unroll
    for (int i = 0; i < 8; i++) {
        int row = bm + ty * 8 + i;
        float* Crow = g_zx + (size_t)row * FD + bn + tx * 8;
#pragma unroll
        for (int jj = 0; jj < 4; jj++) {
            float c0, c1;
            upk2(acc[i][jj], c0, c1);
            int col = bn + tx * 8 + 2 * jj;
            Crow[2 * jj]     = c0 + bih[col]     + bhh[col];
            Crow[2 * jj + 1] = c1 + bih[col + 1] + bhh[col + 1];
        }
    }
}

// ---------------- persistent LSTM: all 128 steps + final linear ----------------
// Grid 128 x 512 (single wave). Block bid owns d-tile [bid*16, +16): 64 whh rows.
// Weights stream as fp16 (half L2 traffic), accumulate fp32 via f32x2 FMA.
__global__ void __launch_bounds__(512, 1)
k_lstm(const float* __restrict__ wlin, const float* __restrict__ blin,
       float* __restrict__ out) {
    __shared__ __align__(16) float hs[Bb][Dd];   // 64 KB: full h
    __shared__ float zbuf[64][9];
    __shared__ float cs_[128];                   // c slice
    int tid = threadIdx.x;
    int wi = tid >> 5;
    int lane = tid & 31;
    int bid = blockIdx.x;
    int d0 = bid * 16;
    int g = wi >> 2;
    int ddb = (wi & 3) * 4;
    // fp16 weight rows: row j = g*Dd + d0 + ddb + r, lane owns halves [lane*4, +4)
    const uint2* wr = (const uint2*)(g_whh_h + ((size_t)g * Dd + d0 + ddb) * Dd) + lane;

    // h_0 = 0 in smem, c = 0
#pragma unroll
    for (int u = 0; u < 8; u++) {
        int fi = tid + u * 512;
        *(float4*)(&hs[0][0] + (size_t)fi * 4) = make_float4(0.f, 0.f, 0.f, 0.f);
    }
    if (tid < 128) cs_[tid] = 0.f;
    __syncthreads();

    for (int t = 0; t < Tt; t++) {
        if (t > 0) {
            const float* h_in = g_h[t & 1];
#pragma unroll
            for (int u = 0; u < 8; u++) {
                int fi = tid + u * 512;
                float4 v = *(const float4*)(h_in + (size_t)fi * 4);
                *(float4*)(&hs[0][0] + (size_t)fi * 4) = v;
            }
            __syncthreads();
        }

        ull acc2[32];
#pragma unroll
        for (int o = 0; o < 32; o++) acc2[o] = 0ull;

        const float* hbase = &hs[0][lane * 4];
        // k-iter: lane owns halves [lane*4 + it*128, +4); uint2 row stride Dd/4
#pragma unroll 4
        for (int it = 0; it < 16; it++) {
            int ko = it * 128;
            int wo = it * 32;                       // uint2 units (128 halves / 4)
            uint2 u0 = wr[wo];
            uint2 u1 = wr[wo + (Dd >> 2)];
            uint2 u2 = wr[wo + 2 * (Dd >> 2)];
            uint2 u3 = wr[wo + 3 * (Dd >> 2)];
            ull w0x = h2f2(u0.x), w0y = h2f2(u0.y);
            ull w1x = h2f2(u1.x), w1y = h2f2(u1.y);
            ull w2x = h2f2(u2.x), w2y = h2f2(u2.y);
            ull w3x = h2f2(u3.x), w3y = h2f2(u3.y);
#pragma unroll
            for (int b = 0; b < Bb; b++) {
                ulonglong2 hv = *(const ulonglong2*)(hbase + b * Dd + ko);
                ffma2(acc2[0 * 8 + b], w0x, hv.x);
                ffma2(acc2[0 * 8 + b], w0y, hv.y);
                ffma2(acc2[1 * 8 + b], w1x, hv.x);
                ffma2(acc2[1 * 8 + b], w1y, hv.y);
                ffma2(acc2[2 * 8 + b], w2x, hv.x);
                ffma2(acc2[2 * 8 + b], w2y, hv.y);
                ffma2(acc2[3 * 8 + b], w3x, hv.x);
                ffma2(acc2[3 * 8 + b], w3y, hv.y);
            }
        }

        float accf[32];
#pragma unroll
        for (int o = 0; o < 32; o++) accf[o] = fsum2(acc2[o]);

        // 5-step butterfly reduction; lane l ends holding output (row l>>3, batch l&7)
#define RSTEP(dd, half)                                                     \
        {                                                                   \
            bool hi = (lane & (dd)) != 0;                                   \
            _Pragma("unroll")                                               \
            for (int i = 0; i < (half); i++) {                              \
                float mine = accf[hi ? (half) + i : i];                     \
                float send = accf[hi ? i : (half) + i];                     \
                float recv = __shfl_xor_sync(0xffffffffu, send, (dd));      \
                accf[i] = mine + recv;                                      \
            }                                                               \
        }
        RSTEP(16, 16)
        RSTEP(8, 8)
        RSTEP(4, 4)
        RSTEP(2, 2)
        RSTEP(1, 1)
#undef RSTEP

        zbuf[wi * 4 + (lane >> 3)][lane & 7] = accf[0];
        __syncthreads();

        if (tid < 128) {
            int dd2 = tid >> 3;
            int bb = tid & 7;
            const float* zx = g_zx + (size_t)(t * Bb + bb) * FD + d0 + dd2;
            float zi = zbuf[0 * 16 + dd2][bb] + zx[0];
            float zf = zbuf[1 * 16 + dd2][bb] + zx[Dd];
            float zg = zbuf[2 * 16 + dd2][bb] + zx[2 * Dd];
            float zo = zbuf[3 * 16 + dd2][bb] + zx[3 * Dd];
            float ig = 1.f / (1.f + expf(-zi));
            float fg = 1.f / (1.f + expf(-zf));
            float gg = tanhf(zg);
            float og = 1.f / (1.f + expf(-zo));
            float cn = fg * cs_[bb * 16 + dd2] + ig * gg;
            cs_[bb * 16 + dd2] = cn;
            g_h[(t + 1) & 1][bb * Dd + d0 + dd2] = og * tanhf(cn);
        }
        __syncthreads();

        // grid barrier for step t
        if (tid == 0) {
            __threadfence();
            atomicAdd(&g_bar[t], 1);
            while (*(volatile int*)&g_bar[t] < 128) { }
            __threadfence();
        }
        __syncthreads();
    }

    // final linear: h_T in g_h[0]. 16 warps: col = bid*4 + (wi&3), batches {2p,2p+1}
    {
        int col = bid * 4 + (wi & 3);
        int p = wi >> 2;
        const float* wl = wlin + (size_t)col * Dd + lane * 4;
        const float* h0 = g_h[0] + (size_t)(2 * p) * Dd + lane * 4;
        const float* h1 = g_h[0] + (size_t)(2 * p + 1) * Dd + lane * 4;
        ull s0 = 0ull, s1 = 0ull;
#pragma unroll 4
        for (int it = 0; it < 16; it++) {
            int ko = it * 128;
            ulonglong2 wv = *(const ulonglong2*)(wl + ko);
            ulonglong2 hv0 = *(const ulonglong2*)(h0 + ko);
            ulonglong2 hv1 = *(const ulonglong2*)(h1 + ko);
            ffma2(s0, wv.x, hv0.x);
            ffma2(s0, wv.y, hv0.y);
            ffma2(s1, wv.x, hv1.x);
            ffma2(s1, wv.y, hv1.y);
        }
        float f0 = fsum2(s0), f1 = fsum2(s1);
#pragma unroll
        for (int d = 16; d; d >>= 1) {
            f0 += __shfl_xor_sync(0xffffffffu, f0, d);
            f1 += __shfl_xor_sync(0xffffffffu, f1, d);
        }
        if (lane == 0) {
            float bl = blin[col];
            out[(2 * p) * Nn + col]     = f0 + bl;
            out[(2 * p + 1) * Nn + col] = f1 + bl;
        }
    }
}

// ---------------- launch ----------------
extern "C" void kernel_launch(void* const* d_in, const int* in_sizes, int n_in,
                              void* d_out, int out_size) {
    const float* x    = (const float*)d_in[0];
    const float* gw   = (const float*)d_in[1];
    const float* as_  = (const float*)d_in[2];
    const float* ad_  = (const float*)d_in[3];
    const float* gb   = (const float*)d_in[4];
    const float* wih  = (const float*)d_in[5];
    const float* whh  = (const float*)d_in[6];
    const float* bih  = (const float*)d_in[7];
    const float* bhh  = (const float*)d_in[8];
    const float* wlin = (const float*)d_in[9];
    const float* blin = (const float*)d_in[10];
    const int*   ei   = (const int*)d_in[11];
    (void)in_sizes; (void)n_in; (void)out_size;

    // w_hh -> fp16 (once per call)
    k_wcvt<<<1024, 512>>>(whh);

    // GAT preprocessing + CSR build (also clears grid-barrier counters)
    k_prep<<<2, 256>>>(gw, as_, ad_);
    k_deg<<<64, 256>>>(ei);
    k_scan<<<1, 512>>>();
    k_fill<<<64, 256>>>(ei);

    // GAT -> g_seq [1024, 2048]
    k_gat_b0<<<Tt, Nn>>>(x, gw, gb);
    k_gat_rest<<<1792, 256>>>(x, gw, gb);

    // Input projection for all timesteps
    {
        dim3 grid(64, 8);
        k_zx<<<grid, 256>>>(wih, bih, bhh);
    }

    // Persistent LSTM (all steps) + final linear
    k_lstm<<<128, 512>>>(wlin, blin, (float*)d_out);
}

// round 7
// speedup vs baseline: 1.8211x; 1.8211x over previous
#include <cuda_runtime.h>
#include <cuda_fp16.h>
#include <math.h>

// Problem constants
#define Bb   8
#define Tt   128
#define Nn   512
#define HIDc 4
#define Dd   2048
#define Ee   16384
#define FD   8192
#define NEG  0.2f

// ---------------- device scratch (no allocations allowed) ----------------
__device__ __align__(256) float g_seq[1024 * 2048];   // [T*B, D] GAT output, 8 MB
__device__ __align__(256) float g_zx[1024u * 8192u];  // [T*B, 4D] x@Wih^T + bias, 32 MB
__device__ __align__(256) unsigned g_wpk[8388608];    // w_hh packed in mma A-frag order, 32 MB
__device__ __align__(256) float  g_h[2][Bb * Dd];     // fp32 hidden (for final linear)
__device__ __align__(256) __half g_h16[2][Bb * Dd];   // fp16 hidden (mma B operand)
__device__ int   g_bar[Tt];
__device__ int   g_deg[Nn];
__device__ int   g_off[Nn];
__device__ int   g_cur[Nn];
__device__ int   g_csr[Ee];
__device__ float g_cs, g_cd;

// ---------------- f32x2 packed FMA helpers ----------------
typedef unsigned long long ull;

__device__ __forceinline__ ull pk2(float x, float y) {
    ull r;
    asm("mov.b64 %0, {%1, %2};" : "=l"(r) : "f"(x), "f"(y));
    return r;
}
__device__ __forceinline__ void ffma2(ull &d, ull a, ull b) {
    asm("fma.rn.f32x2 %0, %1, %2, %0;" : "+l"(d) : "l"(a), "l"(b));
}
__device__ __forceinline__ float fsum2(ull v) {
    float x, y;
    asm("mov.b64 {%0, %1}, %2;" : "=f"(x), "=f"(y) : "l"(v));
    return x + y;
}
__device__ __forceinline__ void upk2(ull v, float &x, float &y) {
    asm("mov.b64 {%0, %1}, %2;" : "=f"(x), "=f"(y) : "l"(v));
}

// ---------------- w_hh fp32 -> fp16, packed in m16n8k16 A-fragment order ----------------
// Consumer (k_lstm): block bid, warp (mi = wi>>2, ks = wi&3), chunk ch (0..31):
//   LDG.128 at g_wpk + (((bid*16 + mi*4 + ks)*32 + ch)*32 + lane)*4  -> regs a0..a3
// Fragment spec (m16n8k16, A row-major 16x16 fp16):
//   reg r: row = (lane>>2) + (r&1)*8,  cols = (lane&3)*2 + ((r>>1)&1)*8 + {0,1}
// Global mapping: w row = mi*Dd + bid*16 + rowlocal, k = ks*512 + ch*16 + collocal
__global__ void k_wcvt(const float* __restrict__ whh) {
    unsigned idx = blockIdx.x * 512 + threadIdx.x;   // one thread per uint4
    if (idx >= 2097152u) return;
    unsigned lane  = idx & 31;
    unsigned ch    = (idx >> 5) & 31;
    unsigned outer = idx >> 10;                      // 0..2047 = bid*16 + mi*4 + ks
    unsigned ks  = outer & 3;
    unsigned mi  = (outer >> 2) & 3;
    unsigned bid = outer >> 4;
    unsigned rbase = mi * Dd + bid * 16 + (lane >> 2);
    unsigned kbase = ks * 512 + ch * 16 + (lane & 3) * 2;
    unsigned r[4];
#pragma unroll
    for (int rr = 0; rr < 4; rr++) {
        unsigned row = rbase + (rr & 1) * 8;
        unsigned k   = kbase + ((rr >> 1) & 1) * 8;
        float2 v = *(const float2*)(whh + (size_t)row * Dd + k);
        __half2 h = __floats2half2_rn(v.x, v.y);
        r[rr] = *reinterpret_cast<unsigned*>(&h);
    }
    ((uint4*)g_wpk)[idx] = make_uint4(r[0], r[1], r[2], r[3]);
}

// ---------------- GAT preprocessing ----------------
__global__ void k_prep(const float* __restrict__ W, const float* __restrict__ as_,
                       const float* __restrict__ ad_) {
    int i = blockIdx.x * blockDim.x + threadIdx.x;
    if (i < Nn) g_deg[i] = 0;
    if (i < Tt) g_bar[i] = 0;
    if (i == 0) {
        float cs = 0.f, cd = 0.f;
        for (int k = 0; k < HIDc; k++) { cs += W[k] * as_[k]; cd += W[k] * ad_[k]; }
        g_cs = cs; g_cd = cd;
    }
}

__global__ void k_deg(const int* __restrict__ ei) {
    int e = blockIdx.x * 256 + threadIdx.x;
    if (e < Ee) atomicAdd(&g_deg[ei[Ee + e]], 1);
}

__global__ void k_scan() {
    __shared__ int s[Nn];
    int i = threadIdx.x;
    int d = g_deg[i];
    s[i] = d;
    __syncthreads();
    for (int off = 1; off < Nn; off <<= 1) {
        int t = 0;
        if (i >= off) t = s[i - off];
        __syncthreads();
        s[i] += t;
        __syncthreads();
    }
    g_off[i] = s[i] - d;
    g_cur[i] = s[i] - d;
}

__global__ void k_fill(const int* __restrict__ ei) {
    int e = blockIdx.x * 256 + threadIdx.x;
    if (e < Ee) {
        int src = ei[e];
        int dst = ei[Ee + e];
        int pos = atomicAdd(&g_cur[dst], 1);
        g_csr[pos] = src;
    }
}

// GAT for batch-0 nodes (only ones with real incoming edges). One block per t.
__global__ void k_gat_b0(const float* __restrict__ x, const float* __restrict__ W,
                         const float* __restrict__ bias) {
    __shared__ float xs[Nn];
    int t = blockIdx.x;
    int i = threadIdx.x;
    xs[i] = x[t * Nn + i];
    __syncthreads();
    float cs = g_cs, cd = g_cd;
    float xi = xs[i];
    float es = xi * (cs + cd);
    es = es > 0.f ? es : NEG * es;
    int beg = g_off[i], end = beg + g_deg[i];
    float m = es;
    for (int e = beg; e < end; e++) {
        float v = cs * xs[g_csr[e]] + cd * xi;
        v = v > 0.f ? v : NEG * v;
        m = fmaxf(m, v);
    }
    float den = expf(es - m);
    float ssum = den * xi;
    for (int e = beg; e < end; e++) {
        float xsrc = xs[g_csr[e]];
        float v = cs * xsrc + cd * xi;
        v = v > 0.f ? v : NEG * v;
        float w = expf(v - m);
        den += w;
        ssum += w * xsrc;
    }
    float s = ssum / den;
    float* o = &g_seq[(size_t)(t * Bb + 0) * Dd + i * HIDc];
#pragma unroll
    for (int k = 0; k < HIDc; k++) {
        float g = fmaf(s, W[k], bias[k]);
        o[k] = g > 0.f ? g : 0.f;
    }
}

// GAT for batches 1..7: self-loop only => s = x
__global__ void k_gat_rest(const float* __restrict__ x, const float* __restrict__ W,
                           const float* __restrict__ bias) {
    int idx = blockIdx.x * 256 + threadIdx.x;
    if (idx >= Tt * (Bb - 1) * Nn) return;
    int t = idx / ((Bb - 1) * Nn);
    int r = idx - t * (Bb - 1) * Nn;
    int b = 1 + (r >> 9);
    int n = r & (Nn - 1);
    float xi = x[((size_t)b * Tt + t) * Nn + n];
    float* o = &g_seq[(size_t)(t * Bb + b) * Dd + n * HIDc];
#pragma unroll
    for (int k = 0; k < HIDc; k++) {
        float g = fmaf(xi, W[k], bias[k]);
        o[k] = g > 0.f ? g : 0.f;
    }
}

// ---------------- input GEMM: Zx[1024,8192] = seq @ w_ih^T + (b_ih+b_hh) ----------------
__global__ void __launch_bounds__(256, 2)
k_zx(const float* __restrict__ Bw, const float* __restrict__ bih,
     const float* __restrict__ bhh) {
    __shared__ __align__(16) float As[16][132];
    __shared__ __align__(16) float Bs[16][132];
    int tid = threadIdx.x;
    int lr = tid >> 2;
    int lk = (tid & 3) * 4;
    int bm = blockIdx.y * 128;
    int bn = blockIdx.x * 128;
    const float* Ap = g_seq + (size_t)(bm + lr) * Dd + lk;
    const float* Bp = Bw + (size_t)(bn + lr) * Dd + lk;
    int tx = tid & 15, ty = tid >> 4;

    ull acc[8][4];
#pragma unroll
    for (int i = 0; i < 8; i++)
#pragma unroll
        for (int j = 0; j < 4; j++) acc[i][j] = pk2(0.f, 0.f);

    for (int k0 = 0; k0 < Dd; k0 += 16) {
#pragma unroll
        for (int hh = 0; hh < 2; hh++) {
            float4 va = *(const float4*)(Ap + (size_t)hh * 64 * Dd + k0);
            As[lk + 0][lr + hh * 64] = va.x;
            As[lk + 1][lr + hh * 64] = va.y;
            As[lk + 2][lr + hh * 64] = va.z;
            As[lk + 3][lr + hh * 64] = va.w;
            float4 vb = *(const float4*)(Bp + (size_t)hh * 64 * Dd + k0);
            Bs[lk + 0][lr + hh * 64] = vb.x;
            Bs[lk + 1][lr + hh * 64] = vb.y;
            Bs[lk + 2][lr + hh * 64] = vb.z;
            Bs[lk + 3][lr + hh * 64] = vb.w;
        }
        __syncthreads();
#pragma unroll
        for (int kk = 0; kk < 16; kk++) {
            float4 a0 = *(const float4*)(&As[kk][ty * 8]);
            float4 a1 = *(const float4*)(&As[kk][ty * 8 + 4]);
            ulonglong2 b0 = *(const ulonglong2*)(&Bs[kk][tx * 8]);
            ulonglong2 b1 = *(const ulonglong2*)(&Bs[kk][tx * 8 + 4]);
            float av[8] = {a0.x, a0.y, a0.z, a0.w, a1.x, a1.y, a1.z, a1.w};
#pragma unroll
            for (int i = 0; i < 8; i++) {
                ull ad = pk2(av[i], av[i]);
                ffma2(acc[i][0], ad, b0.x);
                ffma2(acc[i][1], ad, b0.y);
                ffma2(acc[i][2], ad, b1.x);
                ffma2(acc[i][3], ad, b1.y);
            }
        }
        __syncthreads();
    }
#pragma unroll
    for (int i = 0; i < 8; i++) {
        int row = bm + ty * 8 + i;
        float* Crow = g_zx + (size_t)row * FD + bn + tx * 8;
#pragma unroll
        for (int jj = 0; jj < 4; jj++) {
            float c0, c1;
            upk2(acc[i][jj], c0, c1);
            int col = bn + tx * 8 + 2 * jj;
            Crow[2 * jj]     = c0 + bih[col]     + bhh[col];
            Crow[2 * jj + 1] = c1 + bih[col + 1] + bhh[col + 1];
        }
    }
}

// ---------------- persistent LSTM: all 128 steps via HMMA + final linear ----------------
// Grid 128 x 512 (single wave). Block bid owns d-tile [bid*16, +16): 64 whh rows.
// Warp (mi = gate, ks = k-quarter): 32x mma.sync m16n8k16 per step, A from pre-packed
// global (coalesced LDG.128), B from fp16 h in smem, C fp32. 4-way ks reduce via smem.
#define HROW 2056   // 2048 + 8 halves pad => conflict-free B-frag loads
__global__ void __launch_bounds__(512, 1)
k_lstm(const float* __restrict__ wlin, const float* __restrict__ blin,
       float* __restrict__ out) {
    __shared__ __align__(16) __half h_h[Bb * HROW];  // 32.9 KB fp16 h
    __shared__ __align__(16) float fr[2048];         // 16 warps x 32 lanes x 4 frags
    __shared__ float cs_[128];
    int tid = threadIdx.x;
    int wi = tid >> 5;
    int lane = tid & 31;
    int bid = blockIdx.x;
    int d0 = bid * 16;
    int ks = wi & 3;
    int mi = wi >> 2;
    const uint4* Abase = ((const uint4*)g_wpk) + ((size_t)(bid * 16 + mi * 4 + ks) * 32) * 32;
    int k0base = ks * 512;
    const __half* hb = &h_h[(lane >> 2) * HROW];

    // h_0 = 0 in smem (incl. pad), c = 0
    for (int u = tid; u < Bb * HROW / 8; u += 512)
        ((uint4*)h_h)[u] = make_uint4(0, 0, 0, 0);
    if (tid < 128) cs_[tid] = 0.f;
    __syncthreads();

    for (int t = 0; t < Tt; t++) {
        if (t > 0) {
            const __half* hin = g_h16[t & 1];
#pragma unroll
            for (int u = 0; u < 4; u++) {
                int i = tid + u * 512;            // uint4 idx over 2048 (8 rows x 256)
                int b = i >> 8, k8 = i & 255;
                uint4 v = *(const uint4*)(hin + ((size_t)b << 11) + k8 * 8);
                *(uint4*)(&h_h[b * HROW + k8 * 8]) = v;
            }
            __syncthreads();
        }

        float c0 = 0.f, c1 = 0.f, c2 = 0.f, c3 = 0.f;
#pragma unroll 8
        for (int ch = 0; ch < 32; ch++) {
            uint4 a = Abase[ch * 32 + lane];
            int k = k0base + ch * 16 + (lane & 3) * 2;
            unsigned b0 = *(const unsigned*)(hb + k);
            unsigned b1 = *(const unsigned*)(hb + k + 8);
            asm volatile(
                "mma.sync.aligned.m16n8k16.row.col.f32.f16.f16.f32 "
                "{%0,%1,%2,%3}, {%4,%5,%6,%7}, {%8,%9}, {%0,%1,%2,%3};"
                : "+f"(c0), "+f"(c1), "+f"(c2), "+f"(c3)
                : "r"(a.x), "r"(a.y), "r"(a.z), "r"(a.w), "r"(b0), "r"(b1));
        }
        *(float4*)(&fr[((ks * 4 + mi) * 32 + lane) * 4]) = make_float4(c0, c1, c2, c3);
        __syncthreads();

        if (tid < 128) {
            int dd2 = tid >> 3;       // 0..15
            int bb = tid & 7;
            int li = (dd2 & 7) * 4 + (bb >> 1);
            int ri = (bb & 1) + ((dd2 >> 3) << 1);
            const float* zx = g_zx + (size_t)(t * Bb + bb) * FD + d0 + dd2;
            float z[4];
#pragma unroll
            for (int g4 = 0; g4 < 4; g4++) {
                float s = zx[g4 * Dd];
#pragma unroll
                for (int kss = 0; kss < 4; kss++)
                    s += fr[((kss * 4 + g4) * 32 + li) * 4 + ri];
                z[g4] = s;
            }
            float ig = 1.f / (1.f + expf(-z[0]));
            float fg = 1.f / (1.f + expf(-z[1]));
            float gg = tanhf(z[2]);
            float og = 1.f / (1.f + expf(-z[3]));
            float cn = fg * cs_[bb * 16 + dd2] + ig * gg;
            cs_[bb * 16 + dd2] = cn;
            float hn = og * tanhf(cn);
            int par = (t + 1) & 1;
            g_h[par][bb * Dd + d0 + dd2] = hn;
            g_h16[par][bb * Dd + d0 + dd2] = __float2half(hn);
        }
        __syncthreads();

        // grid barrier for step t
        if (tid == 0) {
            __threadfence();
            atomicAdd(&g_bar[t], 1);
            while (*(volatile int*)&g_bar[t] < 128) { }
            __threadfence();
        }
        __syncthreads();
    }

    // final linear: h_T in g_h[0]. 16 warps: col = bid*4 + (wi&3), batches {2p, 2p+1}
    {
        int col = bid * 4 + (wi & 3);
        int p = wi >> 2;
        const float* wl = wlin + (size_t)col * Dd + lane * 4;
        const float* h0 = g_h[0] + (size_t)(2 * p) * Dd + lane * 4;
        const float* h1 = g_h[0] + (size_t)(2 * p + 1) * Dd + lane * 4;
        ull s0 = 0ull, s1 = 0ull;
#pragma unroll 4
        for (int it = 0; it < 16; it++) {
            int ko = it * 128;
            ulonglong2 wv = *(const ulonglong2*)(wl + ko);
            ulonglong2 hv0 = *(const ulonglong2*)(h0 + ko);
            ulonglong2 hv1 = *(const ulonglong2*)(h1 + ko);
            ffma2(s0, wv.x, hv0.x);
            ffma2(s0, wv.y, hv0.y);
            ffma2(s1, wv.x, hv1.x);
            ffma2(s1, wv.y, hv1.y);
        }
        float f0 = fsum2(s0), f1 = fsum2(s1);
#pragma unroll
        for (int d = 16; d; d >>= 1) {
            f0 += __shfl_xor_sync(0xffffffffu, f0, d);
            f1 += __shfl_xor_sync(0xffffffffu, f1, d);
        }
        if (lane == 0) {
            float bl = blin[col];
            out[(2 * p) * Nn + col]     = f0 + bl;
            out[(2 * p + 1) * Nn + col] = f1 + bl;
        }
    }
}

// ---------------- launch ----------------
extern "C" void kernel_launch(void* const* d_in, const int* in_sizes, int n_in,
                              void* d_out, int out_size) {
    const float* x    = (const float*)d_in[0];
    const float* gw   = (const float*)d_in[1];
    const float* as_  = (const float*)d_in[2];
    const float* ad_  = (const float*)d_in[3];
    const float* gb   = (const float*)d_in[4];
    const float* wih  = (const float*)d_in[5];
    const float* whh  = (const float*)d_in[6];
    const float* bih  = (const float*)d_in[7];
    const float* bhh  = (const float*)d_in[8];
    const float* wlin = (const float*)d_in[9];
    const float* blin = (const float*)d_in[10];
    const int*   ei   = (const int*)d_in[11];
    (void)in_sizes; (void)n_in; (void)out_size;

    // w_hh -> fp16 packed in mma fragment order (once per call)
    k_wcvt<<<4096, 512>>>(whh);

    // GAT preprocessing + CSR build (also clears grid-barrier counters)
    k_prep<<<2, 256>>>(gw, as_, ad_);
    k_deg<<<64, 256>>>(ei);
    k_scan<<<1, 512>>>();
    k_fill<<<64, 256>>>(ei);

    // GAT -> g_seq [1024, 2048]
    k_gat_b0<<<Tt, Nn>>>(x, gw, gb);
    k_gat_rest<<<1792, 256>>>(x, gw, gb);

    // Input projection for all timesteps
    {
        dim3 grid(64, 8);
        k_zx<<<grid, 256>>>(wih, bih, bhh);
    }

    // Persistent LSTM (all steps, HMMA) + final linear
    k_lstm<<<128, 512>>>(wlin, blin, (float*)d_out);
}

// round 8
// speedup vs baseline: 3.3295x; 1.8283x over previous
#include <cuda_runtime.h>
#include <cuda_fp16.h>
#include <math.h>

// Problem constants
#define Bb   8
#define Tt   128
#define Nn   512
#define HIDc 4
#define Dd   2048
#define Ee   16384
#define FD   8192
#define NEG  0.2f

// ---------------- device scratch (no allocations allowed) ----------------
__device__ __align__(256) __half g_seq16[1024 * 2048];  // [T*B, D] GAT out fp16, 4 MB
__device__ __align__(256) float g_zxt[8192u * 1024u];   // Z^T [4D, T*B], 32 MB
__device__ __align__(256) unsigned g_wpk[8388608];      // w_hh packed A-frags, 32 MB
__device__ __align__(256) unsigned g_wpk2[8388608];     // w_ih packed A-frags, 32 MB
__device__ __align__(256) float  g_h[2][Bb * Dd];       // fp32 hidden (final linear)
__device__ __align__(256) __half g_h16[2][Bb * Dd];     // fp16 hidden (mma B operand)
__device__ int   g_bar[Tt];
__device__ int   g_deg[Nn];
__device__ int   g_off[Nn];
__device__ int   g_cur[Nn];
__device__ int   g_csr[Ee];
__device__ float g_cs, g_cd;

// ---------------- helpers ----------------
typedef unsigned long long ull;

__device__ __forceinline__ ull pk2(float x, float y) {
    ull r;
    asm("mov.b64 %0, {%1, %2};" : "=l"(r) : "f"(x), "f"(y));
    return r;
}
__device__ __forceinline__ void ffma2(ull &d, ull a, ull b) {
    asm("fma.rn.f32x2 %0, %1, %2, %0;" : "+l"(d) : "l"(a), "l"(b));
}
__device__ __forceinline__ float fsum2(ull v) {
    float x, y;
    asm("mov.b64 {%0, %1}, %2;" : "=f"(x), "=f"(y) : "l"(v));
    return x + y;
}
__device__ __forceinline__ unsigned smem_u32(const void* p) {
    unsigned a;
    asm("{ .reg .u64 t; cvta.to.shared.u64 t, %1; cvt.u32.u64 %0, t; }"
        : "=r"(a) : "l"(p));
    return a;
}

// ---------------- w_hh fp32 -> fp16, packed in m16n8k16 A-fragment order ----------------
// Consumer (k_lstm): block bid, warp (mi, ks), chunk ch:
//   LDG.128 at g_wpk + (((bid*16 + mi*4 + ks)*32 + ch)*32 + lane)*4
// Frag spec: reg r: row = (lane>>2) + (r&1)*8, col = (lane&3)*2 + ((r>>1)&1)*8 + {0,1}
__global__ void k_wcvt(const float* __restrict__ whh) {
    unsigned idx = blockIdx.x * 512 + threadIdx.x;
    if (idx >= 2097152u) return;
    unsigned lane  = idx & 31;
    unsigned ch    = (idx >> 5) & 31;
    unsigned outer = idx >> 10;
    unsigned ks  = outer & 3;
    unsigned mi  = (outer >> 2) & 3;
    unsigned bid = outer >> 4;
    unsigned rbase = mi * Dd + bid * 16 + (lane >> 2);
    unsigned kbase = ks * 512 + ch * 16 + (lane & 3) * 2;
    unsigned r[4];
#pragma unroll
    for (int rr = 0; rr < 4; rr++) {
        unsigned row = rbase + (rr & 1) * 8;
        unsigned k   = kbase + ((rr >> 1) & 1) * 8;
        float2 v = *(const float2*)(whh + (size_t)row * Dd + k);
        __half2 h = __floats2half2_rn(v.x, v.y);
        r[rr] = *reinterpret_cast<unsigned*>(&h);
    }
    ((uint4*)g_wpk)[idx] = make_uint4(r[0], r[1], r[2], r[3]);
}

// ---------------- w_ih fp32 -> fp16, packed A-frag order for k_zxt ----------------
// Consumer: mtile mt (0..511), kchunk kc (0..127): uint4 at ((mt*128 + kc)*32 + lane)
__global__ void k_wcvt_ih(const float* __restrict__ wih) {
    unsigned idx = blockIdx.x * 512 + threadIdx.x;
    if (idx >= 2097152u) return;
    unsigned lane = idx & 31;
    unsigned kc   = (idx >> 5) & 127;
    unsigned mt   = idx >> 12;
    unsigned rbase = mt * 16 + (lane >> 2);
    unsigned kbase = kc * 16 + (lane & 3) * 2;
    unsigned r[4];
#pragma unroll
    for (int rr = 0; rr < 4; rr++) {
        unsigned row = rbase + (rr & 1) * 8;
        unsigned k   = kbase + ((rr >> 1) & 1) * 8;
        float2 v = *(const float2*)(wih + (size_t)row * Dd + k);
        __half2 h = __floats2half2_rn(v.x, v.y);
        r[rr] = *reinterpret_cast<unsigned*>(&h);
    }
    ((uint4*)g_wpk2)[idx] = make_uint4(r[0], r[1], r[2], r[3]);
}

// ---------------- GAT preprocessing ----------------
__global__ void k_prep(const float* __restrict__ W, const float* __restrict__ as_,
                       const float* __restrict__ ad_) {
    int i = blockIdx.x * blockDim.x + threadIdx.x;
    if (i < Nn) g_deg[i] = 0;
    if (i < Tt) g_bar[i] = 0;
    if (i == 0) {
        float cs = 0.f, cd = 0.f;
        for (int k = 0; k < HIDc; k++) { cs += W[k] * as_[k]; cd += W[k] * ad_[k]; }
        g_cs = cs; g_cd = cd;
    }
}

__global__ void k_deg(const int* __restrict__ ei) {
    int e = blockIdx.x * 256 + threadIdx.x;
    if (e < Ee) atomicAdd(&g_deg[ei[Ee + e]], 1);
}

__global__ void k_scan() {
    __shared__ int s[Nn];
    int i = threadIdx.x;
    int d = g_deg[i];
    s[i] = d;
    __syncthreads();
    for (int off = 1; off < Nn; off <<= 1) {
        int t = 0;
        if (i >= off) t = s[i - off];
        __syncthreads();
        s[i] += t;
        __syncthreads();
    }
    g_off[i] = s[i] - d;
    g_cur[i] = s[i] - d;
}

__global__ void k_fill(const int* __restrict__ ei) {
    int e = blockIdx.x * 256 + threadIdx.x;
    if (e < Ee) {
        int src = ei[e];
        int dst = ei[Ee + e];
        int pos = atomicAdd(&g_cur[dst], 1);
        g_csr[pos] = src;
    }
}

// GAT for batch-0 nodes. One block per t. Writes fp16.
__global__ void k_gat_b0(const float* __restrict__ x, const float* __restrict__ W,
                         const float* __restrict__ bias) {
    __shared__ float xs[Nn];
    int t = blockIdx.x;
    int i = threadIdx.x;
    xs[i] = x[t * Nn + i];
    __syncthreads();
    float cs = g_cs, cd = g_cd;
    float xi = xs[i];
    float es = xi * (cs + cd);
    es = es > 0.f ? es : NEG * es;
    int beg = g_off[i], end = beg + g_deg[i];
    float m = es;
    for (int e = beg; e < end; e++) {
        float v = cs * xs[g_csr[e]] + cd * xi;
        v = v > 0.f ? v : NEG * v;
        m = fmaxf(m, v);
    }
    float den = expf(es - m);
    float ssum = den * xi;
    for (int e = beg; e < end; e++) {
        float xsrc = xs[g_csr[e]];
        float v = cs * xsrc + cd * xi;
        v = v > 0.f ? v : NEG * v;
        float w = expf(v - m);
        den += w;
        ssum += w * xsrc;
    }
    float s = ssum / den;
    float gg[4];
#pragma unroll
    for (int k = 0; k < HIDc; k++) {
        float g = fmaf(s, W[k], bias[k]);
        gg[k] = g > 0.f ? g : 0.f;
    }
    __half2 a = __floats2half2_rn(gg[0], gg[1]);
    __half2 b = __floats2half2_rn(gg[2], gg[3]);
    *(uint2*)(&g_seq16[(size_t)(t * Bb) * Dd + i * HIDc]) =
        make_uint2(*reinterpret_cast<unsigned*>(&a), *reinterpret_cast<unsigned*>(&b));
}

// GAT for batches 1..7: self-loop only => s = x. Writes fp16.
__global__ void k_gat_rest(const float* __restrict__ x, const float* __restrict__ W,
                           const float* __restrict__ bias) {
    int idx = blockIdx.x * 256 + threadIdx.x;
    if (idx >= Tt * (Bb - 1) * Nn) return;
    int t = idx / ((Bb - 1) * Nn);
    int r = idx - t * (Bb - 1) * Nn;
    int b = 1 + (r >> 9);
    int n = r & (Nn - 1);
    float xi = x[((size_t)b * Tt + t) * Nn + n];
    float gg[4];
#pragma unroll
    for (int k = 0; k < HIDc; k++) {
        float g = fmaf(xi, W[k], bias[k]);
        gg[k] = g > 0.f ? g : 0.f;
    }
    __half2 a = __floats2half2_rn(gg[0], gg[1]);
    __half2 bh = __floats2half2_rn(gg[2], gg[3]);
    *(uint2*)(&g_seq16[(size_t)(t * Bb + b) * Dd + n * HIDc]) =
        make_uint2(*reinterpret_cast<unsigned*>(&a), *reinterpret_cast<unsigned*>(&bh));
}

// ---------------- input GEMM on HMMA: Z^T[8192,1024] = w_ih @ seq^T + bias ----------------
// Block 128m x 256n, 512 thr (16 warps: wm=wi>>2 of 4, wn=wi&3 of 4), warp 32m x 64n.
// A: pre-packed w_ih frags from global (coalesced). B: seq16 tiles via cp.async,
// double-buffered ktile=32. C fp32. Epilogue adds (b_ih+b_hh)[m], stores Z^T.
#define BROW 40   // halves per smem B row (32 + 8 pad)
__global__ void __launch_bounds__(512, 1)
k_zxt(const float* __restrict__ bih, const float* __restrict__ bhh) {
    __shared__ __align__(16) __half Bs[2][256 * BROW];   // 2 x 20 KB
    int tid = threadIdx.x;
    int wi = tid >> 5;
    int lane = tid & 31;
    int wm = wi >> 2;
    int wn = wi & 3;
    int bm = blockIdx.y * 128;
    int bn = blockIdx.x * 256;

    // cp.async source/dst for this thread (2 x 16B per tile)
    int li0 = tid * 2;
    int row0 = li0 >> 2, c0 = li0 & 3;
    int li1 = li0 + 1;
    int row1 = li1 >> 2, c1 = li1 & 3;
    const __half* src0 = g_seq16 + (size_t)(bn + row0) * Dd + c0 * 8;
    const __half* src1 = g_seq16 + (size_t)(bn + row1) * Dd + c1 * 8;
    unsigned dst0 = smem_u32(&Bs[0][row0 * BROW + c0 * 8]);
    unsigned dst1 = smem_u32(&Bs[0][row1 * BROW + c1 * 8]);
    const unsigned bufB = 256 * BROW * 2;  // bytes per buffer

    // A pointer: base for this warp (mtiles bm/16 + wm*2 + {0,1})
    const uint4* Ap = ((const uint4*)g_wpk2) + ((size_t)(bm / 16 + wm * 2) * 128) * 32 + lane;

    // B frag base offset (halves) within a buffer
    int bfrag = (wn * 64 + (lane >> 2)) * BROW + (lane & 3) * 2;

    float acc[2][8][4];
#pragma unroll
    for (int a = 0; a < 2; a++)
#pragma unroll
        for (int b = 0; b < 8; b++)
#pragma unroll
            for (int c = 0; c < 4; c++) acc[a][b][c] = 0.f;

    // preload tile 0
    asm volatile("cp.async.cg.shared.global [%0], [%1], 16;" :: "r"(dst0), "l"(src0));
    asm volatile("cp.async.cg.shared.global [%0], [%1], 16;" :: "r"(dst1), "l"(src1));
    asm volatile("cp.async.commit_group;");

    for (int kt = 0; kt < 64; kt++) {
        int buf = kt & 1;
        if (kt + 1 < 64) {
            unsigned off = ((kt + 1) & 1) * bufB;
            asm volatile("cp.async.cg.shared.global [%0], [%1], 16;"
                         :: "r"(dst0 + off), "l"(src0 + (kt + 1) * 32));
            asm volatile("cp.async.cg.shared.global [%0], [%1], 16;"
                         :: "r"(dst1 + off), "l"(src1 + (kt + 1) * 32));
            asm volatile("cp.async.commit_group;");
            asm volatile("cp.async.wait_group 1;");
        } else {
            asm volatile("cp.async.wait_group 0;");
        }
        __syncthreads();

        const __half* Bb_ = &Bs[buf][bfrag];
#pragma unroll
        for (int kk = 0; kk < 2; kk++) {
            int kc = kt * 2 + kk;
            uint4 a0 = Ap[(size_t)(0 * 128 + kc) * 32];
            uint4 a1 = Ap[(size_t)(1 * 128 + kc) * 32];
#pragma unroll
            for (int nt = 0; nt < 8; nt++) {
                unsigned b0 = *(const unsigned*)(Bb_ + nt * 8 * BROW + kk * 16);
                unsigned b1 = *(const unsigned*)(Bb_ + nt * 8 * BROW + kk * 16 + 8);
                asm volatile(
                    "mma.sync.aligned.m16n8k16.row.col.f32.f16.f16.f32 "
                    "{%0,%1,%2,%3}, {%4,%5,%6,%7}, {%8,%9}, {%0,%1,%2,%3};"
                    : "+f"(acc[0][nt][0]), "+f"(acc[0][nt][1]),
                      "+f"(acc[0][nt][2]), "+f"(acc[0][nt][3])
                    : "r"(a0.x), "r"(a0.y), "r"(a0.z), "r"(a0.w), "r"(b0), "r"(b1));
                asm volatile(
                    "mma.sync.aligned.m16n8k16.row.col.f32.f16.f16.f32 "
                    "{%0,%1,%2,%3}, {%4,%5,%6,%7}, {%8,%9}, {%0,%1,%2,%3};"
                    : "+f"(acc[1][nt][0]), "+f"(acc[1][nt][1]),
                      "+f"(acc[1][nt][2]), "+f"(acc[1][nt][3])
                    : "r"(a1.x), "r"(a1.y), "r"(a1.z), "r"(a1.w), "r"(b0), "r"(b1));
            }
        }
        __syncthreads();
    }

    // epilogue: add bias, store Z^T
#pragma unroll
    for (int mtl = 0; mtl < 2; mtl++) {
        int m = bm + wm * 32 + mtl * 16 + (lane >> 2);
        float bA = bih[m] + bhh[m];
        float bB = bih[m + 8] + bhh[m + 8];
#pragma unroll
        for (int nt = 0; nt < 8; nt++) {
            int n = bn + wn * 64 + nt * 8 + (lane & 3) * 2;
            *(float2*)(&g_zxt[(size_t)m * 1024 + n]) =
                make_float2(acc[mtl][nt][0] + bA, acc[mtl][nt][1] + bA);
            *(float2*)(&g_zxt[(size_t)(m + 8) * 1024 + n]) =
                make_float2(acc[mtl][nt][2] + bB, acc[mtl][nt][3] + bB);
        }
    }
}

// ---------------- persistent LSTM: all 128 steps via HMMA + final linear ----------------
#define HROW 2056
__global__ void __launch_bounds__(512, 1)
k_lstm(const float* __restrict__ wlin, const float* __restrict__ blin,
       float* __restrict__ out) {
    __shared__ __align__(16) __half h_h[Bb * HROW];
    __shared__ __align__(16) float fr[2048];
    __shared__ float cs_[128];
    int tid = threadIdx.x;
    int wi = tid >> 5;
    int lane = tid & 31;
    int bid = blockIdx.x;
    int d0 = bid * 16;
    int ks = wi & 3;
    int mi = wi >> 2;
    const uint4* Abase = ((const uint4*)g_wpk) + ((size_t)(bid * 16 + mi * 4 + ks) * 32) * 32;
    int k0base = ks * 512;
    const __half* hb = &h_h[(lane >> 2) * HROW];

    for (int u = tid; u < Bb * HROW / 8; u += 512)
        ((uint4*)h_h)[u] = make_uint4(0, 0, 0, 0);
    if (tid < 128) cs_[tid] = 0.f;
    __syncthreads();

    for (int t = 0; t < Tt; t++) {
        if (t > 0) {
            const __half* hin = g_h16[t & 1];
#pragma unroll
            for (int u = 0; u < 4; u++) {
                int i = tid + u * 512;
                int b = i >> 8, k8 = i & 255;
                uint4 v = *(const uint4*)(hin + ((size_t)b << 11) + k8 * 8);
                *(uint4*)(&h_h[b * HROW + k8 * 8]) = v;
            }
            __syncthreads();
        }

        float c0 = 0.f, c1 = 0.f, c2 = 0.f, c3 = 0.f;
#pragma unroll 8
        for (int ch = 0; ch < 32; ch++) {
            uint4 a = Abase[ch * 32 + lane];
            int k = k0base + ch * 16 + (lane & 3) * 2;
            unsigned b0 = *(const unsigned*)(hb + k);
            unsigned b1 = *(const unsigned*)(hb + k + 8);
            asm volatile(
                "mma.sync.aligned.m16n8k16.row.col.f32.f16.f16.f32 "
                "{%0,%1,%2,%3}, {%4,%5,%6,%7}, {%8,%9}, {%0,%1,%2,%3};"
                : "+f"(c0), "+f"(c1), "+f"(c2), "+f"(c3)
                : "r"(a.x), "r"(a.y), "r"(a.z), "r"(a.w), "r"(b0), "r"(b1));
        }
        *(float4*)(&fr[((ks * 4 + mi) * 32 + lane) * 4]) = make_float4(c0, c1, c2, c3);
        __syncthreads();

        if (tid < 128) {
            int dd2 = tid >> 3;
            int bb = tid & 7;
            int li = (dd2 & 7) * 4 + (bb >> 1);
            int ri = (bb & 1) + ((dd2 >> 3) << 1);
            const float* zxb = g_zxt + (size_t)(d0 + dd2) * 1024 + t * Bb + bb;
            float z[4];
#pragma unroll
            for (int g4 = 0; g4 < 4; g4++) {
                float s = zxb[(size_t)g4 * 2097152];   // (g*2048 rows) * 1024
#pragma unroll
                for (int kss = 0; kss < 4; kss++)
                    s += fr[((kss * 4 + g4) * 32 + li) * 4 + ri];
                z[g4] = s;
            }
            float ig = 1.f / (1.f + expf(-z[0]));
            float fg = 1.f / (1.f + expf(-z[1]));
            float gg = tanhf(z[2]);
            float og = 1.f / (1.f + expf(-z[3]));
            float cn = fg * cs_[bb * 16 + dd2] + ig * gg;
            cs_[bb * 16 + dd2] = cn;
            float hn = og * tanhf(cn);
            int par = (t + 1) & 1;
            g_h[par][bb * Dd + d0 + dd2] = hn;
            g_h16[par][bb * Dd + d0 + dd2] = __float2half(hn);
        }
        __syncthreads();

        if (tid == 0) {
            __threadfence();
            atomicAdd(&g_bar[t], 1);
            while (*(volatile int*)&g_bar[t] < 128) { }
            __threadfence();
        }
        __syncthreads();
    }

    // final linear: h_T in g_h[0]
    {
        int col = bid * 4 + (wi & 3);
        int p = wi >> 2;
        const float* wl = wlin + (size_t)col * Dd + lane * 4;
        const float* h0 = g_h[0] + (size_t)(2 * p) * Dd + lane * 4;
        const float* h1 = g_h[0] + (size_t)(2 * p + 1) * Dd + lane * 4;
        ull s0 = 0ull, s1 = 0ull;
#pragma unroll 4
        for (int it = 0; it < 16; it++) {
            int ko = it * 128;
            ulonglong2 wv = *(const ulonglong2*)(wl + ko);
            ulonglong2 hv0 = *(const ulonglong2*)(h0 + ko);
            ulonglong2 hv1 = *(const ulonglong2*)(h1 + ko);
            ffma2(s0, wv.x, hv0.x);
            ffma2(s0, wv.y, hv0.y);
            ffma2(s1, wv.x, hv1.x);
            ffma2(s1, wv.y, hv1.y);
        }
        float f0 = fsum2(s0), f1 = fsum2(s1);
#pragma unroll
        for (int d = 16; d; d >>= 1) {
            f0 += __shfl_xor_sync(0xffffffffu, f0, d);
            f1 += __shfl_xor_sync(0xffffffffu, f1, d);
        }
        if (lane == 0) {
            float bl = blin[col];
            out[(2 * p) * Nn + col]     = f0 + bl;
            out[(2 * p + 1) * Nn + col] = f1 + bl;
        }
    }
}

// ---------------- launch ----------------
extern "C" void kernel_launch(void* const* d_in, const int* in_sizes, int n_in,
                              void* d_out, int out_size) {
    const float* x    = (const float*)d_in[0];
    const float* gw   = (const float*)d_in[1];
    const float* as_  = (const float*)d_in[2];
    const float* ad_  = (const float*)d_in[3];
    const float* gb   = (const float*)d_in[4];
    const float* wih  = (const float*)d_in[5];
    const float* whh  = (const float*)d_in[6];
    const float* bih  = (const float*)d_in[7];
    const float* bhh  = (const float*)d_in[8];
    const float* wlin = (const float*)d_in[9];
    const float* blin = (const float*)d_in[10];
    const int*   ei   = (const int*)d_in[11];
    (void)in_sizes; (void)n_in; (void)out_size;

    // weight packing (once per call)
    k_wcvt<<<4096, 512>>>(whh);
    k_wcvt_ih<<<4096, 512>>>(wih);

    // GAT preprocessing + CSR build (also clears grid-barrier counters)
    k_prep<<<2, 256>>>(gw, as_, ad_);
    k_deg<<<64, 256>>>(ei);
    k_scan<<<1, 512>>>();
    k_fill<<<64, 256>>>(ei);

    // GAT -> g_seq16 [1024, 2048] fp16
    k_gat_b0<<<Tt, Nn>>>(x, gw, gb);
    k_gat_rest<<<1792, 256>>>(x, gw, gb);

    // Input projection (HMMA): Z^T = w_ih @ seq^T + bias
    {
        dim3 grid(4, 64);
        k_zxt<<<grid, 512>>>(bih, bhh);
    }

    // Persistent LSTM (all steps, HMMA) + final linear
    k_lstm<<<128, 512>>>(wlin, blin, (float*)d_out);
}

// round 9
// speedup vs baseline: 3.6138x; 1.0854x over previous
#include <cuda_runtime.h>
#include <cuda_fp16.h>
#include <math.h>

// Problem constants
#define Bb   8
#define Tt   128
#define Nn   512
#define HIDc 4
#define Dd   2048
#define Ee   16384
#define FD   8192
#define NEG  0.2f

// ---------------- device scratch (no allocations allowed) ----------------
__device__ __align__(256) __half g_seq16[1024 * 2048];  // [T*B, D] GAT out fp16, 4 MB
__device__ __align__(256) float g_zxt[8192u * 1024u];   // Z^T [4D, T*B], 32 MB
__device__ __align__(256) unsigned g_wpk[8388608];      // w_hh packed A-frags, 32 MB
__device__ __align__(256) unsigned g_wpk2[8388608];     // w_ih packed A-frags, 32 MB
__device__ __align__(256) float  g_h[2][Bb * Dd];       // fp32 hidden (final linear)
__device__ __align__(256) __half g_h16[2][Bb * Dd];     // fp16 hidden (mma B operand)
__device__ int   g_bar[Tt];
__device__ int   g_deg[Nn];
__device__ int   g_off[Nn];
__device__ int   g_csr[Ee];
__device__ float g_cs, g_cd;

// ---------------- helpers ----------------
typedef unsigned long long ull;

__device__ __forceinline__ ull pk2(float x, float y) {
    ull r;
    asm("mov.b64 %0, {%1, %2};" : "=l"(r) : "f"(x), "f"(y));
    return r;
}
__device__ __forceinline__ void ffma2(ull &d, ull a, ull b) {
    asm("fma.rn.f32x2 %0, %1, %2, %0;" : "+l"(d) : "l"(a), "l"(b));
}
__device__ __forceinline__ float fsum2(ull v) {
    float x, y;
    asm("mov.b64 {%0, %1}, %2;" : "=f"(x), "=f"(y) : "l"(v));
    return x + y;
}
__device__ __forceinline__ unsigned smem_u32(const void* p) {
    unsigned a;
    asm("{ .reg .u64 t; cvta.to.shared.u64 t, %1; cvt.u32.u64 %0, t; }"
        : "=r"(a) : "l"(p));
    return a;
}

// ---------------- weight packing: whh AND wih -> fp16 m16n8k16 A-frag order ----------------
// Frag spec: reg r: row = (lane>>2) + (r&1)*8, col = (lane&3)*2 + ((r>>1)&1)*8 + {0,1}
// whh consumer: ((bid*16 + mi*4 + ks)*32 + ch)*32 + lane; row = mi*Dd + bid*16 + rl,
//               k = ks*512 + ch*16 + cl
// wih consumer: ((mt*128 + kc)*32 + lane); row = mt*16 + rl, k = kc*16 + cl
__global__ void k_wcvt_all(const float* __restrict__ whh, const float* __restrict__ wih) {
    unsigned idx = blockIdx.x * 512 + threadIdx.x;
    if (idx < 2097152u) {
        unsigned lane  = idx & 31;
        unsigned ch    = (idx >> 5) & 31;
        unsigned outer = idx >> 10;
        unsigned ks  = outer & 3;
        unsigned mi  = (outer >> 2) & 3;
        unsigned bid = outer >> 4;
        unsigned rbase = mi * Dd + bid * 16 + (lane >> 2);
        unsigned kbase = ks * 512 + ch * 16 + (lane & 3) * 2;
        unsigned r[4];
#pragma unroll
        for (int rr = 0; rr < 4; rr++) {
            unsigned row = rbase + (rr & 1) * 8;
            unsigned k   = kbase + ((rr >> 1) & 1) * 8;
            float2 v = *(const float2*)(whh + (size_t)row * Dd + k);
            __half2 h = __floats2half2_rn(v.x, v.y);
            r[rr] = *reinterpret_cast<unsigned*>(&h);
        }
        ((uint4*)g_wpk)[idx] = make_uint4(r[0], r[1], r[2], r[3]);
    } else if (idx < 4194304u) {
        unsigned j = idx - 2097152u;
        unsigned lane = j & 31;
        unsigned kc   = (j >> 5) & 127;
        unsigned mt   = j >> 12;
        unsigned rbase = mt * 16 + (lane >> 2);
        unsigned kbase = kc * 16 + (lane & 3) * 2;
        unsigned r[4];
#pragma unroll
        for (int rr = 0; rr < 4; rr++) {
            unsigned row = rbase + (rr & 1) * 8;
            unsigned k   = kbase + ((rr >> 1) & 1) * 8;
            float2 v = *(const float2*)(wih + (size_t)row * Dd + k);
            __half2 h = __floats2half2_rn(v.x, v.y);
            r[rr] = *reinterpret_cast<unsigned*>(&h);
        }
        ((uint4*)g_wpk2)[j] = make_uint4(r[0], r[1], r[2], r[3]);
    }
}

// ---------------- fused CSR build: consts + degree + scan + fill (1 block) ----------------
__global__ void __launch_bounds__(512)
k_graph(const int* __restrict__ ei, const float* __restrict__ W,
        const float* __restrict__ as_, const float* __restrict__ ad_) {
    __shared__ int sdeg[Nn];
    __shared__ int s[Nn];
    __shared__ int scur[Nn];
    int tid = threadIdx.x;           // 512 == Nn
    if (tid == 0) {
        float cs = 0.f, cd = 0.f;
        for (int k = 0; k < HIDc; k++) { cs += W[k] * as_[k]; cd += W[k] * ad_[k]; }
        g_cs = cs; g_cd = cd;
    }
    sdeg[tid] = 0;
    if (tid < Tt) g_bar[tid] = 0;
    __syncthreads();
    for (int e = tid; e < Ee; e += 512) atomicAdd(&sdeg[ei[Ee + e]], 1);
    __syncthreads();
    int d = sdeg[tid];
    s[tid] = d;
    __syncthreads();
    for (int off = 1; off < Nn; off <<= 1) {
        int t = 0;
        if (tid >= off) t = s[tid - off];
        __syncthreads();
        s[tid] += t;
        __syncthreads();
    }
    g_deg[tid] = d;
    g_off[tid] = s[tid] - d;
    scur[tid] = s[tid] - d;
    __syncthreads();
    for (int e = tid; e < Ee; e += 512) {
        int src = ei[e];
        int dst = ei[Ee + e];
        int pos = atomicAdd(&scur[dst], 1);
        g_csr[pos] = src;
    }
}

// GAT for batch-0 nodes. One block per t. Writes fp16.
__global__ void k_gat_b0(const float* __restrict__ x, const float* __restrict__ W,
                         const float* __restrict__ bias) {
    __shared__ float xs[Nn];
    int t = blockIdx.x;
    int i = threadIdx.x;
    xs[i] = x[t * Nn + i];
    __syncthreads();
    float cs = g_cs, cd = g_cd;
    float xi = xs[i];
    float es = xi * (cs + cd);
    es = es > 0.f ? es : NEG * es;
    int beg = g_off[i], end = beg + g_deg[i];
    float m = es;
    for (int e = beg; e < end; e++) {
        float v = cs * xs[g_csr[e]] + cd * xi;
        v = v > 0.f ? v : NEG * v;
        m = fmaxf(m, v);
    }
    float den = expf(es - m);
    float ssum = den * xi;
    for (int e = beg; e < end; e++) {
        float xsrc = xs[g_csr[e]];
        float v = cs * xsrc + cd * xi;
        v = v > 0.f ? v : NEG * v;
        float w = expf(v - m);
        den += w;
        ssum += w * xsrc;
    }
    float sA = ssum / den;
    float gg[4];
#pragma unroll
    for (int k = 0; k < HIDc; k++) {
        float g = fmaf(sA, W[k], bias[k]);
        gg[k] = g > 0.f ? g : 0.f;
    }
    __half2 a = __floats2half2_rn(gg[0], gg[1]);
    __half2 b = __floats2half2_rn(gg[2], gg[3]);
    *(uint2*)(&g_seq16[(size_t)(t * Bb) * Dd + i * HIDc]) =
        make_uint2(*reinterpret_cast<unsigned*>(&a), *reinterpret_cast<unsigned*>(&b));
}

// GAT for batches 1..7: self-loop only => s = x. Writes fp16.
__global__ void k_gat_rest(const float* __restrict__ x, const float* __restrict__ W,
                           const float* __restrict__ bias) {
    int idx = blockIdx.x * 256 + threadIdx.x;
    if (idx >= Tt * (Bb - 1) * Nn) return;
    int t = idx / ((Bb - 1) * Nn);
    int r = idx - t * (Bb - 1) * Nn;
    int b = 1 + (r >> 9);
    int n = r & (Nn - 1);
    float xi = x[((size_t)b * Tt + t) * Nn + n];
    float gg[4];
#pragma unroll
    for (int k = 0; k < HIDc; k++) {
        float g = fmaf(xi, W[k], bias[k]);
        gg[k] = g > 0.f ? g : 0.f;
    }
    __half2 a = __floats2half2_rn(gg[0], gg[1]);
    __half2 bh = __floats2half2_rn(gg[2], gg[3]);
    *(uint2*)(&g_seq16[(size_t)(t * Bb + b) * Dd + n * HIDc]) =
        make_uint2(*reinterpret_cast<unsigned*>(&a), *reinterpret_cast<unsigned*>(&bh));
}

// ---------------- input GEMM on HMMA: Z^T[8192,1024] = w_ih @ seq^T + bias ----------------
#define BROW 40   // halves per smem B row (32 + 8 pad)
__global__ void __launch_bounds__(512, 1)
k_zxt(const float* __restrict__ bih, const float* __restrict__ bhh) {
    __shared__ __align__(16) __half Bs[2][256 * BROW];
    int tid = threadIdx.x;
    int wi = tid >> 5;
    int lane = tid & 31;
    int wm = wi >> 2;
    int wn = wi & 3;
    int bm = blockIdx.y * 128;
    int bn = blockIdx.x * 256;

    int li0 = tid * 2;
    int row0 = li0 >> 2, c0 = li0 & 3;
    int li1 = li0 + 1;
    int row1 = li1 >> 2, c1 = li1 & 3;
    const __half* src0 = g_seq16 + (size_t)(bn + row0) * Dd + c0 * 8;
    const __half* src1 = g_seq16 + (size_t)(bn + row1) * Dd + c1 * 8;
    unsigned dst0 = smem_u32(&Bs[0][row0 * BROW + c0 * 8]);
    unsigned dst1 = smem_u32(&Bs[0][row1 * BROW + c1 * 8]);
    const unsigned bufB = 256 * BROW * 2;

    const uint4* Ap = ((const uint4*)g_wpk2) + ((size_t)(bm / 16 + wm * 2) * 128) * 32 + lane;
    int bfrag = (wn * 64 + (lane >> 2)) * BROW + (lane & 3) * 2;

    float acc[2][8][4];
#pragma unroll
    for (int a = 0; a < 2; a++)
#pragma unroll
        for (int b = 0; b < 8; b++)
#pragma unroll
            for (int c = 0; c < 4; c++) acc[a][b][c] = 0.f;

    asm volatile("cp.async.cg.shared.global [%0], [%1], 16;" :: "r"(dst0), "l"(src0));
    asm volatile("cp.async.cg.shared.global [%0], [%1], 16;" :: "r"(dst1), "l"(src1));
    asm volatile("cp.async.commit_group;");

    for (int kt = 0; kt < 64; kt++) {
        int buf = kt & 1;
        if (kt + 1 < 64) {
            unsigned off = ((kt + 1) & 1) * bufB;
            asm volatile("cp.async.cg.shared.global [%0], [%1], 16;"
                         :: "r"(dst0 + off), "l"(src0 + (kt + 1) * 32));
            asm volatile("cp.async.cg.shared.global [%0], [%1], 16;"
                         :: "r"(dst1 + off), "l"(src1 + (kt + 1) * 32));
            asm volatile("cp.async.commit_group;");
            asm volatile("cp.async.wait_group 1;");
        } else {
            asm volatile("cp.async.wait_group 0;");
        }
        __syncthreads();

        const __half* Bb_ = &Bs[buf][bfrag];
#pragma unroll
        for (int kk = 0; kk < 2; kk++) {
            int kc = kt * 2 + kk;
            uint4 a0 = Ap[(size_t)(0 * 128 + kc) * 32];
            uint4 a1 = Ap[(size_t)(1 * 128 + kc) * 32];
#pragma unroll
            for (int nt = 0; nt < 8; nt++) {
                unsigned b0 = *(const unsigned*)(Bb_ + nt * 8 * BROW + kk * 16);
                unsigned b1 = *(const unsigned*)(Bb_ + nt * 8 * BROW + kk * 16 + 8);
                asm volatile(
                    "mma.sync.aligned.m16n8k16.row.col.f32.f16.f16.f32 "
                    "{%0,%1,%2,%3}, {%4,%5,%6,%7}, {%8,%9}, {%0,%1,%2,%3};"
                    : "+f"(acc[0][nt][0]), "+f"(acc[0][nt][1]),
                      "+f"(acc[0][nt][2]), "+f"(acc[0][nt][3])
                    : "r"(a0.x), "r"(a0.y), "r"(a0.z), "r"(a0.w), "r"(b0), "r"(b1));
                asm volatile(
                    "mma.sync.aligned.m16n8k16.row.col.f32.f16.f16.f32 "
                    "{%0,%1,%2,%3}, {%4,%5,%6,%7}, {%8,%9}, {%0,%1,%2,%3};"
                    : "+f"(acc[1][nt][0]), "+f"(acc[1][nt][1]),
                      "+f"(acc[1][nt][2]), "+f"(acc[1][nt][3])
                    : "r"(a1.x), "r"(a1.y), "r"(a1.z), "r"(a1.w), "r"(b0), "r"(b1));
            }
        }
        __syncthreads();
    }

#pragma unroll
    for (int mtl = 0; mtl < 2; mtl++) {
        int m = bm + wm * 32 + mtl * 16 + (lane >> 2);
        float bA = bih[m] + bhh[m];
        float bB = bih[m + 8] + bhh[m + 8];
#pragma unroll
        for (int nt = 0; nt < 8; nt++) {
            int n = bn + wn * 64 + nt * 8 + (lane & 3) * 2;
            *(float2*)(&g_zxt[(size_t)m * 1024 + n]) =
                make_float2(acc[mtl][nt][0] + bA, acc[mtl][nt][1] + bA);
            *(float2*)(&g_zxt[(size_t)(m + 8) * 1024 + n]) =
                make_float2(acc[mtl][nt][2] + bB, acc[mtl][nt][3] + bB);
        }
    }
}

// ---------------- persistent LSTM: all 128 steps via HMMA + final linear ----------------
#define HROW 2056
__global__ void __launch_bounds__(512, 1)
k_lstm(const float* __restrict__ wlin, const float* __restrict__ blin,
       float* __restrict__ out) {
    __shared__ __align__(16) __half h_h[Bb * HROW];
    __shared__ __align__(16) float fr[2048];
    __shared__ float cs_[128];
    int tid = threadIdx.x;
    int wi = tid >> 5;
    int lane = tid & 31;
    int bid = blockIdx.x;
    int d0 = bid * 16;
    int ks = wi & 3;
    int mi = wi >> 2;
    const uint4* Abase = ((const uint4*)g_wpk) + ((size_t)(bid * 16 + mi * 4 + ks) * 32) * 32;
    int k0base = ks * 512;
    const __half* hb = &h_h[(lane >> 2) * HROW];

    // gate-thread indices (tid < 128)
    int dd2 = tid >> 3;
    int bb = tid & 7;
    const float* zxb = g_zxt + (size_t)(d0 + dd2) * 1024 + bb;

    for (int u = tid; u < Bb * HROW / 8; u += 512)
        ((uint4*)h_h)[u] = make_uint4(0, 0, 0, 0);
    if (tid < 128) cs_[tid] = 0.f;
    __syncthreads();

    for (int t = 0; t < Tt; t++) {
        // prefetch this step's zx gate values (independent of barrier / h)
        float zpre[4];
        if (tid < 128) {
            const float* zp = zxb + t * Bb;
#pragma unroll
            for (int g4 = 0; g4 < 4; g4++) zpre[g4] = zp[(size_t)g4 * 2097152];
        }

        if (t > 0) {
            const __half* hin = g_h16[t & 1];
#pragma unroll
            for (int u = 0; u < 4; u++) {
                int i = tid + u * 512;
                int b = i >> 8, k8 = i & 255;
                uint4 v = *(const uint4*)(hin + ((size_t)b << 11) + k8 * 8);
                *(uint4*)(&h_h[b * HROW + k8 * 8]) = v;
            }
            __syncthreads();
        }

        float c0 = 0.f, c1 = 0.f, c2 = 0.f, c3 = 0.f;
#pragma unroll 8
        for (int ch = 0; ch < 32; ch++) {
            uint4 a = Abase[ch * 32 + lane];
            int k = k0base + ch * 16 + (lane & 3) * 2;
            unsigned b0 = *(const unsigned*)(hb + k);
            unsigned b1 = *(const unsigned*)(hb + k + 8);
            asm volatile(
                "mma.sync.aligned.m16n8k16.row.col.f32.f16.f16.f32 "
                "{%0,%1,%2,%3}, {%4,%5,%6,%7}, {%8,%9}, {%0,%1,%2,%3};"
                : "+f"(c0), "+f"(c1), "+f"(c2), "+f"(c3)
                : "r"(a.x), "r"(a.y), "r"(a.z), "r"(a.w), "r"(b0), "r"(b1));
        }
        *(float4*)(&fr[((ks * 4 + mi) * 32 + lane) * 4]) = make_float4(c0, c1, c2, c3);
        __syncthreads();

        if (tid < 128) {
            int li = (dd2 & 7) * 4 + (bb >> 1);
            int ri = (bb & 1) + ((dd2 >> 3) << 1);
            float z[4];
#pragma unroll
            for (int g4 = 0; g4 < 4; g4++) {
                float s = zpre[g4];
#pragma unroll
                for (int kss = 0; kss < 4; kss++)
                    s += fr[((kss * 4 + g4) * 32 + li) * 4 + ri];
                z[g4] = s;
            }
            float ig = 1.f / (1.f + expf(-z[0]));
            float fg = 1.f / (1.f + expf(-z[1]));
            float gg = tanhf(z[2]);
            float og = 1.f / (1.f + expf(-z[3]));
            float cn = fg * cs_[bb * 16 + dd2] + ig * gg;
            cs_[bb * 16 + dd2] = cn;
            float hn = og * tanhf(cn);
            int par = (t + 1) & 1;
            g_h16[par][bb * Dd + d0 + dd2] = __float2half(hn);
            g_h[par][bb * Dd + d0 + dd2] = hn;
        }
        __syncthreads();

        // grid barrier: release-arrive + acquire-poll (CG grid.sync pattern)
        if (tid == 0) {
            int* bar = &g_bar[t];
            asm volatile("red.release.gpu.add.u32 [%0], 1;" :: "l"(bar) : "memory");
            unsigned v;
            do {
                asm volatile("ld.acquire.gpu.u32 %0, [%1];" : "=r"(v) : "l"(bar) : "memory");
            } while (v < 128);
        }
        __syncthreads();
    }

    // final linear: h_T in g_h[0]
    {
        int col = bid * 4 + (wi & 3);
        int p = wi >> 2;
        const float* wl = wlin + (size_t)col * Dd + lane * 4;
        const float* h0 = g_h[0] + (size_t)(2 * p) * Dd + lane * 4;
        const float* h1 = g_h[0] + (size_t)(2 * p + 1) * Dd + lane * 4;
        ull s0 = 0ull, s1 = 0ull;
#pragma unroll 4
        for (int it = 0; it < 16; it++) {
            int ko = it * 128;
            ulonglong2 wv = *(const ulonglong2*)(wl + ko);
            ulonglong2 hv0 = *(const ulonglong2*)(h0 + ko);
            ulonglong2 hv1 = *(const ulonglong2*)(h1 + ko);
            ffma2(s0, wv.x, hv0.x);
            ffma2(s0, wv.y, hv0.y);
            ffma2(s1, wv.x, hv1.x);
            ffma2(s1, wv.y, hv1.y);
        }
        float f0 = fsum2(s0), f1 = fsum2(s1);
#pragma unroll
        for (int d = 16; d; d >>= 1) {
            f0 += __shfl_xor_sync(0xffffffffu, f0, d);
            f1 += __shfl_xor_sync(0xffffffffu, f1, d);
        }
        if (lane == 0) {
            float bl = blin[col];
            out[(2 * p) * Nn + col]     = f0 + bl;
            out[(2 * p + 1) * Nn + col] = f1 + bl;
        }
    }
}

// ---------------- launch ----------------
extern "C" void kernel_launch(void* const* d_in, const int* in_sizes, int n_in,
                              void* d_out, int out_size) {
    const float* x    = (const float*)d_in[0];
    const float* gw   = (const float*)d_in[1];
    const float* as_  = (const float*)d_in[2];
    const float* ad_  = (const float*)d_in[3];
    const float* gb   = (const float*)d_in[4];
    const float* wih  = (const float*)d_in[5];
    const float* whh  = (const float*)d_in[6];
    const float* bih  = (const float*)d_in[7];
    const float* bhh  = (const float*)d_in[8];
    const float* wlin = (const float*)d_in[9];
    const float* blin = (const float*)d_in[10];
    const int*   ei   = (const int*)d_in[11];
    (void)in_sizes; (void)n_in; (void)out_size;

    // pack both weight matrices (one launch)
    k_wcvt_all<<<8192, 512>>>(whh, wih);

    // fused CSR build + consts + barrier clear (one block)
    k_graph<<<1, 512>>>(ei, gw, as_, ad_);

    // GAT -> g_seq16 [1024, 2048] fp16
    k_gat_b0<<<Tt, Nn>>>(x, gw, gb);
    k_gat_rest<<<1792, 256>>>(x, gw, gb);

    // Input projection (HMMA): Z^T = w_ih @ seq^T + bias
    {
        dim3 grid(4, 64);
        k_zxt<<<grid, 512>>>(bih, bhh);
    }

    // Persistent LSTM (all steps, HMMA) + final linear
    k_lstm<<<128, 512>>>(wlin, blin, (float*)d_out);
}

// round 10
// speedup vs baseline: 3.7001x; 1.0239x over previous
#include <cuda_runtime.h>
#include <cuda_fp16.h>
#include <math.h>

// Problem constants
#define Bb   8
#define Tt   128
#define Nn   512
#define HIDc 4
#define Dd   2048
#define Ee   16384
#define FD   8192
#define NEG  0.2f

// k_lstm smem layout (dynamic, opt-in)
#define HROW   2056
#define NCACHE 22                     // k-chunks cached in smem (of 32)
#define NGLOB  (32 - NCACHE)
#define SM_HH    0
#define SM_FR    32896                // 8*2056*2
#define SM_CS    (SM_FR + 8192)
#define SM_WS    (SM_CS + 512)        // 41600, 16B aligned
#define SM_TOTAL (SM_WS + 16 * NCACHE * 32 * 16)   // + 176 KB = 221824

// ---------------- device scratch (no allocations allowed) ----------------
__device__ __align__(256) __half g_seq16[1024 * 2048];  // [T*B, D] GAT out fp16, 4 MB
__device__ __align__(256) float g_zxt[8192u * 1024u];   // Z^T [4D, T*B], 32 MB
__device__ __align__(256) unsigned g_wpk[8388608];      // w_hh packed A-frags, 32 MB
__device__ __align__(256) unsigned g_wpk2[8388608];     // w_ih packed A-frags, 32 MB
__device__ __align__(256) float  g_h[2][Bb * Dd];       // fp32 hidden (final linear)
__device__ __align__(256) __half g_h16[2][Bb * Dd];     // fp16 hidden (mma B operand)
__device__ int   g_bar[Tt];
__device__ int   g_deg[Nn];
__device__ int   g_off[Nn];
__device__ int   g_csr[Ee];
__device__ float g_cs, g_cd;

// ---------------- helpers ----------------
typedef unsigned long long ull;

__device__ __forceinline__ ull pk2(float x, float y) {
    ull r;
    asm("mov.b64 %0, {%1, %2};" : "=l"(r) : "f"(x), "f"(y));
    return r;
}
__device__ __forceinline__ void ffma2(ull &d, ull a, ull b) {
    asm("fma.rn.f32x2 %0, %1, %2, %0;" : "+l"(d) : "l"(a), "l"(b));
}
__device__ __forceinline__ float fsum2(ull v) {
    float x, y;
    asm("mov.b64 {%0, %1}, %2;" : "=f"(x), "=f"(y) : "l"(v));
    return x + y;
}
__device__ __forceinline__ unsigned smem_u32(const void* p) {
    unsigned a;
    asm("{ .reg .u64 t; cvta.to.shared.u64 t, %1; cvt.u32.u64 %0, t; }"
        : "=r"(a) : "l"(p));
    return a;
}

// ---------------- weight packing: whh AND wih -> fp16 m16n8k16 A-frag order ----------------
__global__ void k_wcvt_all(const float* __restrict__ whh, const float* __restrict__ wih) {
    unsigned idx = blockIdx.x * 512 + threadIdx.x;
    if (idx < 2097152u) {
        unsigned lane  = idx & 31;
        unsigned ch    = (idx >> 5) & 31;
        unsigned outer = idx >> 10;
        unsigned ks  = outer & 3;
        unsigned mi  = (outer >> 2) & 3;
        unsigned bid = outer >> 4;
        unsigned rbase = mi * Dd + bid * 16 + (lane >> 2);
        unsigned kbase = ks * 512 + ch * 16 + (lane & 3) * 2;
        unsigned r[4];
#pragma unroll
        for (int rr = 0; rr < 4; rr++) {
            unsigned row = rbase + (rr & 1) * 8;
            unsigned k   = kbase + ((rr >> 1) & 1) * 8;
            float2 v = *(const float2*)(whh + (size_t)row * Dd + k);
            __half2 h = __floats2half2_rn(v.x, v.y);
            r[rr] = *reinterpret_cast<unsigned*>(&h);
        }
        ((uint4*)g_wpk)[idx] = make_uint4(r[0], r[1], r[2], r[3]);
    } else if (idx < 4194304u) {
        unsigned j = idx - 2097152u;
        unsigned lane = j & 31;
        unsigned kc   = (j >> 5) & 127;
        unsigned mt   = j >> 12;
        unsigned rbase = mt * 16 + (lane >> 2);
        unsigned kbase = kc * 16 + (lane & 3) * 2;
        unsigned r[4];
#pragma unroll
        for (int rr = 0; rr < 4; rr++) {
            unsigned row = rbase + (rr & 1) * 8;
            unsigned k   = kbase + ((rr >> 1) & 1) * 8;
            float2 v = *(const float2*)(wih + (size_t)row * Dd + k);
            __half2 h = __floats2half2_rn(v.x, v.y);
            r[rr] = *reinterpret_cast<unsigned*>(&h);
        }
        ((uint4*)g_wpk2)[j] = make_uint4(r[0], r[1], r[2], r[3]);
    }
}

// ---------------- fused CSR build: consts + degree + scan + fill (1 block) ----------------
__global__ void __launch_bounds__(512)
k_graph(const int* __restrict__ ei, const float* __restrict__ W,
        const float* __restrict__ as_, const float* __restrict__ ad_) {
    __shared__ int sdeg[Nn];
    __shared__ int s[Nn];
    __shared__ int scur[Nn];
    int tid = threadIdx.x;
    if (tid == 0) {
        float cs = 0.f, cd = 0.f;
        for (int k = 0; k < HIDc; k++) { cs += W[k] * as_[k]; cd += W[k] * ad_[k]; }
        g_cs = cs; g_cd = cd;
    }
    sdeg[tid] = 0;
    if (tid < Tt) g_bar[tid] = 0;
    __syncthreads();
    for (int e = tid; e < Ee; e += 512) atomicAdd(&sdeg[ei[Ee + e]], 1);
    __syncthreads();
    int d = sdeg[tid];
    s[tid] = d;
    __syncthreads();
    for (int off = 1; off < Nn; off <<= 1) {
        int t = 0;
        if (tid >= off) t = s[tid - off];
        __syncthreads();
        s[tid] += t;
        __syncthreads();
    }
    g_deg[tid] = d;
    g_off[tid] = s[tid] - d;
    scur[tid] = s[tid] - d;
    __syncthreads();
    for (int e = tid; e < Ee; e += 512) {
        int src = ei[e];
        int dst = ei[Ee + e];
        int pos = atomicAdd(&scur[dst], 1);
        g_csr[pos] = src;
    }
}

// GAT for batch-0 nodes. One block per t. Writes fp16.
__global__ void k_gat_b0(const float* __restrict__ x, const float* __restrict__ W,
                         const float* __restrict__ bias) {
    __shared__ float xs[Nn];
    int t = blockIdx.x;
    int i = threadIdx.x;
    xs[i] = x[t * Nn + i];
    __syncthreads();
    float cs = g_cs, cd = g_cd;
    float xi = xs[i];
    float es = xi * (cs + cd);
    es = es > 0.f ? es : NEG * es;
    int beg = g_off[i], end = beg + g_deg[i];
    float m = es;
    for (int e = beg; e < end; e++) {
        float v = cs * xs[g_csr[e]] + cd * xi;
        v = v > 0.f ? v : NEG * v;
        m = fmaxf(m, v);
    }
    float den = expf(es - m);
    float ssum = den * xi;
    for (int e = beg; e < end; e++) {
        float xsrc = xs[g_csr[e]];
        float v = cs * xsrc + cd * xi;
        v = v > 0.f ? v : NEG * v;
        float w = expf(v - m);
        den += w;
        ssum += w * xsrc;
    }
    float sA = ssum / den;
    float gg[4];
#pragma unroll
    for (int k = 0; k < HIDc; k++) {
        float g = fmaf(sA, W[k], bias[k]);
        gg[k] = g > 0.f ? g : 0.f;
    }
    __half2 a = __floats2half2_rn(gg[0], gg[1]);
    __half2 b = __floats2half2_rn(gg[2], gg[3]);
    *(uint2*)(&g_seq16[(size_t)(t * Bb) * Dd + i * HIDc]) =
        make_uint2(*reinterpret_cast<unsigned*>(&a), *reinterpret_cast<unsigned*>(&b));
}

// GAT for batches 1..7: self-loop only => s = x. Writes fp16.
__global__ void k_gat_rest(const float* __restrict__ x, const float* __restrict__ W,
                           const float* __restrict__ bias) {
    int idx = blockIdx.x * 256 + threadIdx.x;
    if (idx >= Tt * (Bb - 1) * Nn) return;
    int t = idx / ((Bb - 1) * Nn);
    int r = idx - t * (Bb - 1) * Nn;
    int b = 1 + (r >> 9);
    int n = r & (Nn - 1);
    float xi = x[((size_t)b * Tt + t) * Nn + n];
    float gg[4];
#pragma unroll
    for (int k = 0; k < HIDc; k++) {
        float g = fmaf(xi, W[k], bias[k]);
        gg[k] = g > 0.f ? g : 0.f;
    }
    __half2 a = __floats2half2_rn(gg[0], gg[1]);
    __half2 bh = __floats2half2_rn(gg[2], gg[3]);
    *(uint2*)(&g_seq16[(size_t)(t * Bb + b) * Dd + n * HIDc]) =
        make_uint2(*reinterpret_cast<unsigned*>(&a), *reinterpret_cast<unsigned*>(&bh));
}

// ---------------- input GEMM on HMMA: Z^T[8192,1024] = w_ih @ seq^T + bias ----------------
#define BROW 40
__global__ void __launch_bounds__(512, 1)
k_zxt(const float* __restrict__ bih, const float* __restrict__ bhh) {
    __shared__ __align__(16) __half Bs[2][256 * BROW];
    int tid = threadIdx.x;
    int wi = tid >> 5;
    int lane = tid & 31;
    int wm = wi >> 2;
    int wn = wi & 3;
    int bm = blockIdx.y * 128;
    int bn = blockIdx.x * 256;

    int li0 = tid * 2;
    int row0 = li0 >> 2, c0 = li0 & 3;
    int li1 = li0 + 1;
    int row1 = li1 >> 2, c1 = li1 & 3;
    const __half* src0 = g_seq16 + (size_t)(bn + row0) * Dd + c0 * 8;
    const __half* src1 = g_seq16 + (size_t)(bn + row1) * Dd + c1 * 8;
    unsigned dst0 = smem_u32(&Bs[0][row0 * BROW + c0 * 8]);
    unsigned dst1 = smem_u32(&Bs[0][row1 * BROW + c1 * 8]);
    const unsigned bufB = 256 * BROW * 2;

    const uint4* Ap = ((const uint4*)g_wpk2) + ((size_t)(bm / 16 + wm * 2) * 128) * 32 + lane;
    int bfrag = (wn * 64 + (lane >> 2)) * BROW + (lane & 3) * 2;

    float acc[2][8][4];
#pragma unroll
    for (int a = 0; a < 2; a++)
#pragma unroll
        for (int b = 0; b < 8; b++)
#pragma unroll
            for (int c = 0; c < 4; c++) acc[a][b][c] = 0.f;

    asm volatile("cp.async.cg.shared.global [%0], [%1], 16;" :: "r"(dst0), "l"(src0));
    asm volatile("cp.async.cg.shared.global [%0], [%1], 16;" :: "r"(dst1), "l"(src1));
    asm volatile("cp.async.commit_group;");

    for (int kt = 0; kt < 64; kt++) {
        int buf = kt & 1;
        if (kt + 1 < 64) {
            unsigned off = ((kt + 1) & 1) * bufB;
            asm volatile("cp.async.cg.shared.global [%0], [%1], 16;"
                         :: "r"(dst0 + off), "l"(src0 + (kt + 1) * 32));
            asm volatile("cp.async.cg.shared.global [%0], [%1], 16;"
                         :: "r"(dst1 + off), "l"(src1 + (kt + 1) * 32));
            asm volatile("cp.async.commit_group;");
            asm volatile("cp.async.wait_group 1;");
        } else {
            asm volatile("cp.async.wait_group 0;");
        }
        __syncthreads();

        const __half* Bb_ = &Bs[buf][bfrag];
#pragma unroll
        for (int kk = 0; kk < 2; kk++) {
            int kc = kt * 2 + kk;
            uint4 a0 = Ap[(size_t)(0 * 128 + kc) * 32];
            uint4 a1 = Ap[(size_t)(1 * 128 + kc) * 32];
#pragma unroll
            for (int nt = 0; nt < 8; nt++) {
                unsigned b0 = *(const unsigned*)(Bb_ + nt * 8 * BROW + kk * 16);
                unsigned b1 = *(const unsigned*)(Bb_ + nt * 8 * BROW + kk * 16 + 8);
                asm volatile(
                    "mma.sync.aligned.m16n8k16.row.col.f32.f16.f16.f32 "
                    "{%0,%1,%2,%3}, {%4,%5,%6,%7}, {%8,%9}, {%0,%1,%2,%3};"
                    : "+f"(acc[0][nt][0]), "+f"(acc[0][nt][1]),
                      "+f"(acc[0][nt][2]), "+f"(acc[0][nt][3])
                    : "r"(a0.x), "r"(a0.y), "r"(a0.z), "r"(a0.w), "r"(b0), "r"(b1));
                asm volatile(
                    "mma.sync.aligned.m16n8k16.row.col.f32.f16.f16.f32 "
                    "{%0,%1,%2,%3}, {%4,%5,%6,%7}, {%8,%9}, {%0,%1,%2,%3};"
                    : "+f"(acc[1][nt][0]), "+f"(acc[1][nt][1]),
                      "+f"(acc[1][nt][2]), "+f"(acc[1][nt][3])
                    : "r"(a1.x), "r"(a1.y), "r"(a1.z), "r"(a1.w), "r"(b0), "r"(b1));
            }
        }
        __syncthreads();
    }

#pragma unroll
    for (int mtl = 0; mtl < 2; mtl++) {
        int m = bm + wm * 32 + mtl * 16 + (lane >> 2);
        float bA = bih[m] + bhh[m];
        float bB = bih[m + 8] + bhh[m + 8];
#pragma unroll
        for (int nt = 0; nt < 8; nt++) {
            int n = bn + wn * 64 + nt * 8 + (lane & 3) * 2;
            *(float2*)(&g_zxt[(size_t)m * 1024 + n]) =
                make_float2(acc[mtl][nt][0] + bA, acc[mtl][nt][1] + bA);
            *(float2*)(&g_zxt[(size_t)(m + 8) * 1024 + n]) =
                make_float2(acc[mtl][nt][2] + bB, acc[mtl][nt][3] + bB);
        }
    }
}

// ---------------- persistent LSTM: 128 steps, weights mostly pinned in SMEM ----------------
__global__ void __launch_bounds__(512, 1)
k_lstm(const float* __restrict__ wlin, const float* __restrict__ blin,
       float* __restrict__ out) {
    extern __shared__ __align__(16) char smem[];
    __half* h_h = (__half*)(smem + SM_HH);     // 8 x HROW fp16
    float*  fr  = (float*)(smem + SM_FR);      // 16 warps x 32 x 4
    float*  cs_ = (float*)(smem + SM_CS);      // c slice
    uint4*  ws  = (uint4*)(smem + SM_WS);      // weight cache: 16 warps x NCACHE x 32

    int tid = threadIdx.x;
    int wi = tid >> 5;
    int lane = tid & 31;
    int bid = blockIdx.x;
    int d0 = bid * 16;
    int ks = wi & 3;
    int mi = wi >> 2;
    const uint4* Abase = ((const uint4*)g_wpk) + ((size_t)(bid * 16 + mi * 4 + ks) * 32) * 32;
    int k0base = ks * 512;
    const __half* hb = &h_h[(lane >> 2) * HROW];
    uint4* wsw = ws + wi * (NCACHE * 32);

    int dd2 = tid >> 3;
    int bb = tid & 7;
    const float* zxb = g_zxt + (size_t)(d0 + dd2) * 1024 + bb;

    // preload weight cache (chunks 0..NCACHE-1), zero h, zero c
#pragma unroll
    for (int ch = 0; ch < NCACHE; ch++)
        wsw[ch * 32 + lane] = Abase[ch * 32 + lane];
    for (int u = tid; u < Bb * HROW / 8; u += 512)
        ((uint4*)h_h)[u] = make_uint4(0, 0, 0, 0);
    if (tid < 128) cs_[tid] = 0.f;
    __syncthreads();

    for (int t = 0; t < Tt; t++) {
        float zpre[4];
        if (tid < 128) {
            const float* zp = zxb + t * Bb;
#pragma unroll
            for (int g4 = 0; g4 < 4; g4++) zpre[g4] = zp[(size_t)g4 * 2097152];
        }

        if (t > 0) {
            const __half* hin = g_h16[t & 1];
#pragma unroll
            for (int u = 0; u < 4; u++) {
                int i = tid + u * 512;
                int b = i >> 8, k8 = i & 255;
                uint4 v = *(const uint4*)(hin + ((size_t)b << 11) + k8 * 8);
                *(uint4*)(&h_h[b * HROW + k8 * 8]) = v;
            }
            __syncthreads();
        }

        float c0 = 0.f, c1 = 0.f, c2 = 0.f, c3 = 0.f;
        // L2-streamed chunks first: LDGs issue early (MLP), latency hides under smem mmas
#pragma unroll
        for (int ci = 0; ci < NGLOB; ci++) {
            int ch = NCACHE + ci;
            uint4 a = Abase[ch * 32 + lane];
            int k = k0base + ch * 16 + (lane & 3) * 2;
            unsigned b0 = *(const unsigned*)(hb + k);
            unsigned b1 = *(const unsigned*)(hb + k + 8);
            asm volatile(
                "mma.sync.aligned.m16n8k16.row.col.f32.f16.f16.f32 "
                "{%0,%1,%2,%3}, {%4,%5,%6,%7}, {%8,%9}, {%0,%1,%2,%3};"
                : "+f"(c0), "+f"(c1), "+f"(c2), "+f"(c3)
                : "r"(a.x), "r"(a.y), "r"(a.z), "r"(a.w), "r"(b0), "r"(b1));
        }
        // smem-cached chunks
#pragma unroll
        for (int ch = 0; ch < NCACHE; ch++) {
            uint4 a = wsw[ch * 32 + lane];
            int k = k0base + ch * 16 + (lane & 3) * 2;
            unsigned b0 = *(const unsigned*)(hb + k);
            unsigned b1 = *(const unsigned*)(hb + k + 8);
            asm volatile(
                "mma.sync.aligned.m16n8k16.row.col.f32.f16.f16.f32 "
                "{%0,%1,%2,%3}, {%4,%5,%6,%7}, {%8,%9}, {%0,%1,%2,%3};"
                : "+f"(c0), "+f"(c1), "+f"(c2), "+f"(c3)
                : "r"(a.x), "r"(a.y), "r"(a.z), "r"(a.w), "r"(b0), "r"(b1));
        }
        *(float4*)(&fr[((ks * 4 + mi) * 32 + lane) * 4]) = make_float4(c0, c1, c2, c3);
        __syncthreads();

        if (tid < 128) {
            int li = (dd2 & 7) * 4 + (bb >> 1);
            int ri = (bb & 1) + ((dd2 >> 3) << 1);
            float z[4];
#pragma unroll
            for (int g4 = 0; g4 < 4; g4++) {
                float s = zpre[g4];
#pragma unroll
                for (int kss = 0; kss < 4; kss++)
                    s += fr[((kss * 4 + g4) * 32 + li) * 4 + ri];
                z[g4] = s;
            }
            float ig = 1.f / (1.f + expf(-z[0]));
            float fg = 1.f / (1.f + expf(-z[1]));
            float gg = tanhf(z[2]);
            float og = 1.f / (1.f + expf(-z[3]));
            float cn = fg * cs_[bb * 16 + dd2] + ig * gg;
            cs_[bb * 16 + dd2] = cn;
            float hn = og * tanhf(cn);
            int par = (t + 1) & 1;
            g_h16[par][bb * Dd + d0 + dd2] = __float2half(hn);
            g_h[par][bb * Dd + d0 + dd2] = hn;
        }
        __syncthreads();

        if (tid == 0) {
            int* bar = &g_bar[t];
            asm volatile("red.release.gpu.add.u32 [%0], 1;" :: "l"(bar) : "memory");
            unsigned v;
            do {
                asm volatile("ld.acquire.gpu.u32 %0, [%1];" : "=r"(v) : "l"(bar) : "memory");
            } while (v < 128);
        }
        __syncthreads();
    }

    // final linear: h_T in g_h[0]
    {
        int col = bid * 4 + (wi & 3);
        int p = wi >> 2;
        const float* wl = wlin + (size_t)col * Dd + lane * 4;
        const float* h0 = g_h[0] + (size_t)(2 * p) * Dd + lane * 4;
        const float* h1 = g_h[0] + (size_t)(2 * p + 1) * Dd + lane * 4;
        ull s0 = 0ull, s1 = 0ull;
#pragma unroll 4
        for (int it = 0; it < 16; it++) {
            int ko = it * 128;
            ulonglong2 wv = *(const ulonglong2*)(wl + ko);
            ulonglong2 hv0 = *(const ulonglong2*)(h0 + ko);
            ulonglong2 hv1 = *(const ulonglong2*)(h1 + ko);
            ffma2(s0, wv.x, hv0.x);
            ffma2(s0, wv.y, hv0.y);
            ffma2(s1, wv.x, hv1.x);
            ffma2(s1, wv.y, hv1.y);
        }
        float f0 = fsum2(s0), f1 = fsum2(s1);
#pragma unroll
        for (int d = 16; d; d >>= 1) {
            f0 += __shfl_xor_sync(0xffffffffu, f0, d);
            f1 += __shfl_xor_sync(0xffffffffu, f1, d);
        }
        if (lane == 0) {
            float bl = blin[col];
            out[(2 * p) * Nn + col]     = f0 + bl;
            out[(2 * p + 1) * Nn + col] = f1 + bl;
        }
    }
}

// ---------------- launch ----------------
extern "C" void kernel_launch(void* const* d_in, const int* in_sizes, int n_in,
                              void* d_out, int out_size) {
    const float* x    = (const float*)d_in[0];
    const float* gw   = (const float*)d_in[1];
    const float* as_  = (const float*)d_in[2];
    const float* ad_  = (const float*)d_in[3];
    const float* gb   = (const float*)d_in[4];
    const float* wih  = (const float*)d_in[5];
    const float* whh  = (const float*)d_in[6];
    const float* bih  = (const float*)d_in[7];
    const float* bhh  = (const float*)d_in[8];
    const float* wlin = (const float*)d_in[9];
    const float* blin = (const float*)d_in[10];
    const int*   ei   = (const int*)d_in[11];
    (void)in_sizes; (void)n_in; (void)out_size;

    static int smem_set = 0;
    if (!smem_set) {
        cudaFuncSetAttribute(k_lstm, cudaFuncAttributeMaxDynamicSharedMemorySize, SM_TOTAL);
        smem_set = 1;
    }

    // pack both weight matrices (one launch)
    k_wcvt_all<<<8192, 512>>>(whh, wih);

    // fused CSR build + consts + barrier clear (one block)
    k_graph<<<1, 512>>>(ei, gw, as_, ad_);

    // GAT -> g_seq16 [1024, 2048] fp16
    k_gat_b0<<<Tt, Nn>>>(x, gw, gb);
    k_gat_rest<<<1792, 256>>>(x, gw, gb);

    // Input projection (HMMA): Z^T = w_ih @ seq^T + bias
    {
        dim3 grid(4, 64);
        k_zxt<<<grid, 512>>>(bih, bhh);
    }

    // Persistent LSTM (all steps, HMMA + smem-pinned weights) + final linear
    k_lstm<<<128, 512, SM_TOTAL>>>(wlin, blin, (float*)d_out);
}